// round 13
// baseline (speedup 1.0000x reference)
#include <cuda_runtime.h>
#include <cuda_fp16.h>
#include <math.h>

#define BB 4
#define SS 1024
#define IN 1024
#define OUT 1024
#define NH 8
#define NE 16
#define PROJ 128
#define BT (BB*SS)
#define RLEN (2*SS-1)

// ---------------- scratch ----------------------------------------------------
__device__ float    g_selval[BT*NH];
__device__ int      g_selidx[BT*NH];
__device__ int      g_cnt[NE];
__device__ int      g_list[NE*BT];
__device__ unsigned g_kh  [(size_t)BT*64];             // K * sc, fp16x2
__device__ unsigned g_vh  [(size_t)BT*64];             // V, fp16x2
__device__ float    g_pemb[(size_t)RLEN*IN];
__device__ unsigned g_kpos_h[(size_t)(RLEN+1)*64];     // kpos * sc, fp16x2 (+pad row)
__device__ unsigned g_qh  [(size_t)BB*NH*SS*64];       // Q * sc, fp16x2
__device__ unsigned g_r   [(size_t)BT*NH*64];          // gated attn out, fp16x2

// ---------------- fp16 helpers ----------------------------------------------
__device__ __forceinline__ unsigned pk2(float x, float y) {
    __half2 h = __floats2half2_rn(x, y);
    return *reinterpret_cast<unsigned*>(&h);
}
__device__ __forceinline__ void mmaf16(float c[4], const unsigned a[4],
                                       const unsigned b[2]) {
    asm volatile(
        "mma.sync.aligned.m16n8k16.row.col.f32.f16.f16.f32 "
        "{%0,%1,%2,%3},{%4,%5,%6,%7},{%8,%9},{%0,%1,%2,%3};"
        : "+f"(c[0]), "+f"(c[1]), "+f"(c[2]), "+f"(c[3])
        : "r"(a[0]), "r"(a[1]), "r"(a[2]), "r"(a[3]),
          "r"(b[0]), "r"(b[1]));
}
__device__ __forceinline__ void cpasync16(void* smem, const void* gmem) {
    unsigned saddr = (unsigned)__cvta_generic_to_shared(smem);
    asm volatile("cp.async.cg.shared.global [%0], [%1], 16;\n"
                 :: "r"(saddr), "l"(gmem));
}

// tile geometry for generic GEMM
#define TW 40
#define STG_H (128*TW)
#define TG_SMEM (4*STG_H*2)
#define QX_SMEM (TG_SMEM + 128*4)

// ---------------- fp16 tensor GEMM, double-buffered ------------------------
// TRANSB=0: B row-major KxN. TRANSB=1: B row-major NxK (A @ B^T).
// alphaMode: 0 plain fp32 C, 2 split-kv fp16 epilogue (k*sc | v),
//            3 kpos fp16 epilogue (*sqrt(scale) -> g_kpos_h)
template<int TRANSB>
__global__ __launch_bounds__(256, 2)
void tgemm(const float* __restrict__ A, const float* __restrict__ Bm,
           float* __restrict__ C,
           int M, int N, int K, int lda, int ldb, int ldc,
           const float* __restrict__ scalep, int alphaMode)
{
    extern __shared__ half hsm[];
    half* AsBase = hsm;
    half* BsBase = hsm + 2*STG_H;

    const float* Ap = A;
    const float* Bp = Bm;
    float*       Cp = C;
    int m0 = blockIdx.y * 128;
    int n0 = blockIdx.x * 128;

    int tid  = threadIdx.x;
    int wid  = tid >> 5, lane = tid & 31;
    int wm0  = (wid & 1) * 64;
    int wn0  = (wid >> 1) * 32;
    int lg   = lane >> 2;
    int lt   = lane & 3;

    float c[4][4][4];
    #pragma unroll
    for (int i = 0; i < 4; i++)
        #pragma unroll
        for (int j = 0; j < 4; j++)
            #pragma unroll
            for (int q = 0; q < 4; q++) c[i][j][q] = 0.f;

    float4 ra[4];
    float4 rb4[4];
    float  cv[16];

    auto ldA = [&](int k0) {
        #pragma unroll
        for (int i = 0; i < 4; i++) {
            int m  = i * 32 + (tid >> 3);
            int kk = (tid & 7) * 4;
            ra[i] = make_float4(0.f, 0.f, 0.f, 0.f);
            if (m0 + m < M)
                ra[i] = *reinterpret_cast<const float4*>(Ap + (long)(m0 + m) * lda + k0 + kk);
        }
    };
    auto ldB = [&](int k0) {
        if (TRANSB == 0) {
            int n    = tid & 127;
            int kseg = (tid >> 7) * 16;
            const float* src = Bp + (long)(k0 + kseg) * ldb + n0 + n;
            #pragma unroll
            for (int j = 0; j < 16; j++) cv[j] = src[(long)j * ldb];
        } else {
            #pragma unroll
            for (int i = 0; i < 4; i++) {
                int nn = i * 32 + (tid >> 3);
                int kk = (tid & 7) * 4;
                rb4[i] = make_float4(0.f, 0.f, 0.f, 0.f);
                if (n0 + nn < N)
                    rb4[i] = *reinterpret_cast<const float4*>(Bp + (long)(n0 + nn) * ldb + k0 + kk);
            }
        }
    };
    auto stAB = [&](int buf) {
        half* As = AsBase + buf * STG_H;
        half* Bs = BsBase + buf * STG_H;
        #pragma unroll
        for (int i = 0; i < 4; i++) {
            int m  = i * 32 + (tid >> 3);
            int kk = (tid & 7) * 4;
            uint2 w;
            w.x = pk2(ra[i].x, ra[i].y);
            w.y = pk2(ra[i].z, ra[i].w);
            *reinterpret_cast<uint2*>(&As[m * TW + kk]) = w;
        }
        if (TRANSB == 0) {
            int n    = tid & 127;
            int kseg = (tid >> 7) * 16;
            #pragma unroll
            for (int j2 = 0; j2 < 4; j2++) {
                uint2 w;
                w.x = pk2(cv[j2*4+0], cv[j2*4+1]);
                w.y = pk2(cv[j2*4+2], cv[j2*4+3]);
                *reinterpret_cast<uint2*>(&Bs[n * TW + kseg + j2*4]) = w;
            }
        } else {
            #pragma unroll
            for (int i = 0; i < 4; i++) {
                int nn = i * 32 + (tid >> 3);
                int kk = (tid & 7) * 4;
                uint2 w;
                w.x = pk2(rb4[i].x, rb4[i].y);
                w.y = pk2(rb4[i].z, rb4[i].w);
                *reinterpret_cast<uint2*>(&Bs[nn * TW + kk]) = w;
            }
        }
    };
    auto domma = [&](int buf) {
        half* As = AsBase + buf * STG_H;
        half* Bs = BsBase + buf * STG_H;
        #pragma unroll
        for (int ks = 0; ks < 2; ks++) {
            int kb = ks * 16;
            unsigned a[4][4], b[4][2];
            #pragma unroll
            for (int mt = 0; mt < 4; mt++) {
                int r = wm0 + mt * 16 + lg;
                a[mt][0] = *reinterpret_cast<unsigned*>(&As[r * TW + kb + 2*lt]);
                a[mt][1] = *reinterpret_cast<unsigned*>(&As[(r + 8) * TW + kb + 2*lt]);
                a[mt][2] = *reinterpret_cast<unsigned*>(&As[r * TW + kb + 2*lt + 8]);
                a[mt][3] = *reinterpret_cast<unsigned*>(&As[(r + 8) * TW + kb + 2*lt + 8]);
            }
            #pragma unroll
            for (int nt = 0; nt < 4; nt++) {
                int cn = wn0 + nt * 8 + lg;
                b[nt][0] = *reinterpret_cast<unsigned*>(&Bs[cn * TW + kb + 2*lt]);
                b[nt][1] = *reinterpret_cast<unsigned*>(&Bs[cn * TW + kb + 2*lt + 8]);
            }
            #pragma unroll
            for (int mt = 0; mt < 4; mt++)
                #pragma unroll
                for (int nt = 0; nt < 4; nt++)
                    mmaf16(c[mt][nt], a[mt], b[nt]);
        }
    };

    int nk = K / 32;
    ldA(0); ldB(0);
    stAB(0);
    __syncthreads();
    for (int ki = 0; ki < nk; ki++) {
        if (ki + 1 < nk) { ldA((ki + 1) * 32); ldB((ki + 1) * 32); }
        domma(ki & 1);
        if (ki + 1 < nk) {
            stAB((ki + 1) & 1);
            __syncthreads();
        }
    }

    if (alphaMode == 2) {
        float sc = sqrtf(scalep[0]);
        #pragma unroll
        for (int mt = 0; mt < 4; mt++) {
            #pragma unroll
            for (int nt = 0; nt < 4; nt++) {
                #pragma unroll
                for (int ri = 0; ri < 2; ri++) {
                    int r  = m0 + wm0 + mt * 16 + lg + ri * 8;
                    int cc = n0 + wn0 + nt * 8 + 2 * lt;
                    float v0 = c[mt][nt][ri * 2 + 0];
                    float v1 = c[mt][nt][ri * 2 + 1];
                    if (cc < PROJ)
                        g_kh[(size_t)r * 64 + (cc >> 1)] = pk2(sc * v0, sc * v1);
                    else
                        g_vh[(size_t)r * 64 + ((cc - PROJ) >> 1)] = pk2(v0, v1);
                }
            }
        }
        return;
    }
    if (alphaMode == 3) {
        float sc = sqrtf(scalep[0]);
        #pragma unroll
        for (int mt = 0; mt < 4; mt++) {
            #pragma unroll
            for (int ri = 0; ri < 2; ri++) {
                int r = m0 + wm0 + mt * 16 + lg + ri * 8;
                if (r >= M) continue;
                #pragma unroll
                for (int nt = 0; nt < 4; nt++) {
                    int cc = n0 + wn0 + nt * 8 + 2 * lt;
                    g_kpos_h[(size_t)r * 64 + (cc >> 1)] =
                        pk2(sc * c[mt][nt][ri * 2 + 0], sc * c[mt][nt][ri * 2 + 1]);
                }
            }
        }
        return;
    }

    #pragma unroll
    for (int mt = 0; mt < 4; mt++) {
        #pragma unroll
        for (int nt = 0; nt < 4; nt++) {
            int r  = m0 + wm0 + mt * 16 + lg;
            int cc = n0 + wn0 + nt * 8 + 2 * lt;
            if (r < M) {
                if (cc     < N) Cp[(long)r * ldc + cc]     = c[mt][nt][0];
                if (cc + 1 < N) Cp[(long)r * ldc + cc + 1] = c[mt][nt][1];
            }
            if (r + 8 < M) {
                if (cc     < N) Cp[(long)(r + 8) * ldc + cc]     = c[mt][nt][2];
                if (cc + 1 < N) Cp[(long)(r + 8) * ldc + cc + 1] = c[mt][nt][3];
            }
        }
    }
}

// ---------------- expert-bucketed q projection (fp16 MMA, fp16 out) ---------
__global__ __launch_bounds__(256, 2)
void qexp_kernel(const float* __restrict__ curr, const float* __restrict__ dtq,
                 const float* __restrict__ scalep)
{
    extern __shared__ half hsm[];
    half* AsBase = hsm;
    half* BsBase = hsm + 2*STG_H;
    int*  ent    = (int*)(hsm + 4*STG_H);

    int e   = blockIdx.z;
    int cnt = g_cnt[e];
    int t0  = blockIdx.y * 128;
    if (t0 >= cnt) return;

    int tid  = threadIdx.x;
    if (tid < 128)
        ent[tid] = (t0 + tid < cnt) ? g_list[e * BT + t0 + tid] : -1;
    __syncthreads();

    const float* Bp = dtq + (size_t)e * IN * PROJ;

    int wid  = tid >> 5, lane = tid & 31;
    int wm0  = (wid & 1) * 64;
    int wn0  = (wid >> 1) * 32;
    int lg   = lane >> 2;
    int lt   = lane & 3;

    int tok4[4];
    #pragma unroll
    for (int i = 0; i < 4; i++) {
        int m = i * 32 + (tid >> 3);
        int en = ent[m];
        tok4[i] = (en >= 0) ? (en >> 3) : -1;
    }

    float c[4][4][4];
    #pragma unroll
    for (int i = 0; i < 4; i++)
        #pragma unroll
        for (int j = 0; j < 4; j++)
            #pragma unroll
            for (int q = 0; q < 4; q++) c[i][j][q] = 0.f;

    float4 ra[4];
    float  cv[16];
    auto ldA = [&](int k0) {
        int kk = (tid & 7) * 4;
        #pragma unroll
        for (int i = 0; i < 4; i++) {
            ra[i] = make_float4(0.f, 0.f, 0.f, 0.f);
            if (tok4[i] >= 0)
                ra[i] = *reinterpret_cast<const float4*>(curr + (size_t)tok4[i] * IN + k0 + kk);
        }
    };
    auto ldB = [&](int k0) {
        int n    = tid & 127;
        int kseg = (tid >> 7) * 16;
        const float* src = Bp + (size_t)(k0 + kseg) * PROJ + n;
        #pragma unroll
        for (int j = 0; j < 16; j++) cv[j] = src[(size_t)j * PROJ];
    };
    auto stAB = [&](int buf) {
        half* As = AsBase + buf * STG_H;
        half* Bs = BsBase + buf * STG_H;
        int kk = (tid & 7) * 4;
        #pragma unroll
        for (int i = 0; i < 4; i++) {
            int m = i * 32 + (tid >> 3);
            uint2 w;
            w.x = pk2(ra[i].x, ra[i].y);
            w.y = pk2(ra[i].z, ra[i].w);
            *reinterpret_cast<uint2*>(&As[m * TW + kk]) = w;
        }
        int n    = tid & 127;
        int kseg = (tid >> 7) * 16;
        #pragma unroll
        for (int j2 = 0; j2 < 4; j2++) {
            uint2 w;
            w.x = pk2(cv[j2*4+0], cv[j2*4+1]);
            w.y = pk2(cv[j2*4+2], cv[j2*4+3]);
            *reinterpret_cast<uint2*>(&Bs[n * TW + kseg + j2*4]) = w;
        }
    };
    auto domma = [&](int buf) {
        half* As = AsBase + buf * STG_H;
        half* Bs = BsBase + buf * STG_H;
        #pragma unroll
        for (int ks = 0; ks < 2; ks++) {
            int kb = ks * 16;
            unsigned a[4][4], b[4][2];
            #pragma unroll
            for (int mt = 0; mt < 4; mt++) {
                int r = wm0 + mt * 16 + lg;
                a[mt][0] = *reinterpret_cast<unsigned*>(&As[r * TW + kb + 2*lt]);
                a[mt][1] = *reinterpret_cast<unsigned*>(&As[(r + 8) * TW + kb + 2*lt]);
                a[mt][2] = *reinterpret_cast<unsigned*>(&As[r * TW + kb + 2*lt + 8]);
                a[mt][3] = *reinterpret_cast<unsigned*>(&As[(r + 8) * TW + kb + 2*lt + 8]);
            }
            #pragma unroll
            for (int nt = 0; nt < 4; nt++) {
                int cn = wn0 + nt * 8 + lg;
                b[nt][0] = *reinterpret_cast<unsigned*>(&Bs[cn * TW + kb + 2*lt]);
                b[nt][1] = *reinterpret_cast<unsigned*>(&Bs[cn * TW + kb + 2*lt + 8]);
            }
            #pragma unroll
            for (int mt = 0; mt < 4; mt++)
                #pragma unroll
                for (int nt = 0; nt < 4; nt++)
                    mmaf16(c[mt][nt], a[mt], b[nt]);
        }
    };

    ldA(0); ldB(0);
    stAB(0);
    __syncthreads();
    for (int ki = 0; ki < 32; ki++) {
        if (ki + 1 < 32) { ldA((ki + 1) * 32); ldB((ki + 1) * 32); }
        domma(ki & 1);
        if (ki + 1 < 32) { stAB((ki + 1) & 1); __syncthreads(); }
    }

    float alpha = sqrtf(scalep[0]);
    #pragma unroll
    for (int mt = 0; mt < 4; mt++) {
        #pragma unroll
        for (int ri = 0; ri < 2; ri++) {
            int rl = wm0 + mt * 16 + lg + ri * 8;
            int en = ent[rl];
            if (en < 0) continue;
            int token = en >> 3, h = en & 7;
            int b = token >> 10, s = token & 1023;
            unsigned* dst = g_qh + ((size_t)((b * NH + h) * SS + s)) * 64;
            #pragma unroll
            for (int nt = 0; nt < 4; nt++) {
                int cc = wn0 + nt * 8 + 2 * lt;
                dst[cc >> 1] = pk2(alpha * c[mt][nt][ri * 2 + 0],
                                   alpha * c[mt][nt][ri * 2 + 1]);
            }
        }
    }
}

// ---------------- bucketed output projection (fp16 MMA, atomic add) ---------
#define FQW 136
__global__ __launch_bounds__(256, 2)
void obucket_kernel(const float* __restrict__ oproj, float* __restrict__ out)
{
    extern __shared__ half hsm[];
    half* As = hsm;                       // 128 x 136
    half* Bs = hsm + 128*FQW;             // 128 x 136
    int*  ent = (int*)(hsm + 2*128*FQW);

    int e   = blockIdx.z;
    int cnt = g_cnt[e];
    int t0  = blockIdx.y * 128;
    if (t0 >= cnt) return;
    int n0  = blockIdx.x * 128;

    int tid = threadIdx.x;
    if (tid < 128)
        ent[tid] = (t0 + tid < cnt) ? g_list[e * BT + t0 + tid] : -1;
    __syncthreads();

    #pragma unroll
    for (int it = 0; it < 8; it++) {
        int lin = it * 256 + tid;
        int r = lin >> 4, c4 = lin & 15;
        int en = ent[r];
        uint4 v = make_uint4(0, 0, 0, 0);
        if (en >= 0)
            v = reinterpret_cast<const uint4*>(g_r)[(size_t)en * 16 + c4];
        *reinterpret_cast<uint4*>(&As[r * FQW + c4 * 8]) = v;
    }
    {
        int n    = tid & 127;
        int kseg = (tid >> 7) * 64;
        const float* src = oproj + (size_t)e * PROJ * OUT + (size_t)kseg * OUT + n0 + n;
        #pragma unroll
        for (int j2 = 0; j2 < 32; j2++) {
            float v0 = src[(size_t)(2*j2) * OUT];
            float v1 = src[(size_t)(2*j2+1) * OUT];
            *reinterpret_cast<unsigned*>(&Bs[n * FQW + kseg + 2*j2]) = pk2(v0, v1);
        }
    }
    __syncthreads();

    int wid = tid >> 5, lane = tid & 31;
    int wm0 = (wid & 1) * 64;
    int wn0 = (wid >> 1) * 32;
    int lg  = lane >> 2;
    int lt  = lane & 3;

    float c[4][4][4];
    #pragma unroll
    for (int i = 0; i < 4; i++)
        #pragma unroll
        for (int j = 0; j < 4; j++)
            #pragma unroll
            for (int q = 0; q < 4; q++) c[i][j][q] = 0.f;

    #pragma unroll
    for (int ks = 0; ks < 8; ks++) {
        int kb = ks * 16;
        unsigned a[4][4], b[4][2];
        #pragma unroll
        for (int mt = 0; mt < 4; mt++) {
            int r = wm0 + mt * 16 + lg;
            a[mt][0] = *reinterpret_cast<unsigned*>(&As[r * FQW + kb + 2*lt]);
            a[mt][1] = *reinterpret_cast<unsigned*>(&As[(r + 8) * FQW + kb + 2*lt]);
            a[mt][2] = *reinterpret_cast<unsigned*>(&As[r * FQW + kb + 2*lt + 8]);
            a[mt][3] = *reinterpret_cast<unsigned*>(&As[(r + 8) * FQW + kb + 2*lt + 8]);
        }
        #pragma unroll
        for (int nt = 0; nt < 4; nt++) {
            int cn = wn0 + nt * 8 + lg;
            b[nt][0] = *reinterpret_cast<unsigned*>(&Bs[cn * FQW + kb + 2*lt]);
            b[nt][1] = *reinterpret_cast<unsigned*>(&Bs[cn * FQW + kb + 2*lt + 8]);
        }
        #pragma unroll
        for (int mt = 0; mt < 4; mt++)
            #pragma unroll
            for (int nt = 0; nt < 4; nt++)
                mmaf16(c[mt][nt], a[mt], b[nt]);
    }

    #pragma unroll
    for (int mt = 0; mt < 4; mt++) {
        #pragma unroll
        for (int ri = 0; ri < 2; ri++) {
            int rl = wm0 + mt * 16 + lg + ri * 8;
            int en = ent[rl];
            if (en < 0) continue;
            int token = en >> 3;
            float* orow = out + (size_t)token * OUT;
            #pragma unroll
            for (int nt = 0; nt < 4; nt++) {
                int cc = n0 + wn0 + nt * 8 + 2 * lt;
                atomicAdd(&orow[cc],     c[mt][nt][ri * 2 + 0]);
                atomicAdd(&orow[cc + 1], c[mt][nt][ri * 2 + 1]);
            }
        }
    }
}

// ---------------- bucket build ----------------------------------------------
__global__ void qbucket_kernel()
{
    int i = blockIdx.x * 256 + threadIdx.x;
    if (i >= BT * NH) return;
    int e = g_selidx[i];
    int pos = atomicAdd(&g_cnt[e], 1);
    g_list[e * BT + pos] = i;
}

// ---------------- fused flash attention + relative-position band -------------
#define GW 198
__global__ __launch_bounds__(256)
void flash_kernel()
{
    extern __shared__ char smc[];
    half*     Qs   = (half*)smc;                        // 64 x 136
    half*     Ps   = Qs + 64*FQW;                       // 64 x 136
    half*     Kt   = Ps + 64*FQW;                       // 128 x 136
    half*     Kp   = Kt + 128*FQW;                      // 192 x 136 (kpos window)
    unsigned* Vt2  = (unsigned*)(Kp + 192*FQW);         // 64 x 136 (paired V)
    float*    Gs   = (float*)(Vt2 + 64*FQW);            // 64 x 198
    float*    redm = Gs + 64*GW;                        // 256
    float*    reds = redm + 256;                        // 256

    int zh = blockIdx.y;
    int b  = zh >> 3, h = zh & 7;
    int s0 = blockIdx.x * 64;
    int tid = threadIdx.x;
    int wid = tid >> 5, lane = tid & 31;
    int lg = lane >> 2, lt = lane & 3;
    int wm0 = (wid & 1) * 32;
    int wn0 = (wid >> 1) * 32;
    // G warp tiling: 16-row group + 9-tile half-window anchored at ws
    int gm = (wid & 3) * 16;
    int ws = 48 - gm;
    int ghalf = wid >> 2;
    int gc0 = ws + ghalf * 72;

    // async prefetch of K tile + kpos window for iteration kt
    auto prefetchKKp = [&](int kt) {
        int t0  = kt * 128;
        int bt0 = b * SS + t0;
        int base = t0 - s0 + 960;
        const uint4* kbase = reinterpret_cast<const uint4*>(g_kh + (size_t)bt0 * 64);
        #pragma unroll
        for (int it = 0; it < 8; it++) {
            int lin = it * 256 + tid;
            int r = lin >> 4, c4 = lin & 15;
            cpasync16(&Kt[r * FQW + c4 * 8], kbase + r * 16 + c4);
        }
        const uint4* kp4 = reinterpret_cast<const uint4*>(g_kpos_h);
        #pragma unroll
        for (int it = 0; it < 12; it++) {
            int lin = it * 256 + tid;
            int w = lin >> 4, c4 = lin & 15;
            cpasync16(&Kp[w * FQW + c4 * 8], kp4 + (size_t)(base + w) * 16 + c4);
        }
        asm volatile("cp.async.commit_group;\n");
    };

    // prefetch kt=0 under the Q load
    prefetchKKp(0);

    // Q tile 64x128 halves, direct fp16 copy
    {
        const uint4* qbase = reinterpret_cast<const uint4*>(g_qh + (size_t)(zh * SS + s0) * 64);
        #pragma unroll
        for (int it = 0; it < 4; it++) {
            int lin = it * 256 + tid;
            int r = lin >> 4, c4 = lin & 15;
            *reinterpret_cast<uint4*>(&Qs[r * FQW + c4 * 8]) = qbase[r * 16 + c4];
        }
    }

    float o[2][4][4];
    float mrow[2][2], lrow[2][2];
    #pragma unroll
    for (int mt = 0; mt < 2; mt++) {
        mrow[mt][0] = mrow[mt][1] = -1e30f;
        lrow[mt][0] = lrow[mt][1] = 0.f;
        #pragma unroll
        for (int nt = 0; nt < 4; nt++)
            #pragma unroll
            for (int q = 0; q < 4; q++) o[mt][nt][q] = 0.f;
    }

    for (int kt = 0; kt < 8; kt++) {
        int bt0 = b * SS + kt * 128;
        // V tile paired from fp16 (synchronous; Vt2 free per previous iter's last sync)
        {
            const unsigned* vbase = g_vh + (size_t)bt0 * 64;
            #pragma unroll
            for (int it = 0; it < 8; it++) {
                int lin = it * 256 + tid;
                int tp = lin >> 5, p0 = (lin & 31) * 4;
                uint2 x = *reinterpret_cast<const uint2*>(vbase + (size_t)(2*tp) * 64 + (p0 >> 1));
                uint2 y = *reinterpret_cast<const uint2*>(vbase + (size_t)(2*tp + 1) * 64 + (p0 >> 1));
                uint4 w;
                w.x = __byte_perm(x.x, y.x, 0x5410);
                w.y = __byte_perm(x.x, y.x, 0x7632);
                w.z = __byte_perm(x.y, y.y, 0x5410);
                w.w = __byte_perm(x.y, y.y, 0x7632);
                *reinterpret_cast<uint4*>(&Vt2[tp * FQW + p0]) = w;
            }
        }
        asm volatile("cp.async.wait_group 0;\n" ::: "memory");
        __syncthreads();   // Kt, Kp, Vt2 all visible

        // --- G = Q @ Kp^T, band-trimmed: 16 rows x 72 cols per warp ---
        {
            float gg[9][4];
            #pragma unroll
            for (int nt = 0; nt < 9; nt++)
                #pragma unroll
                for (int q = 0; q < 4; q++) gg[nt][q] = 0.f;
            #pragma unroll
            for (int ks = 0; ks < 8; ks++) {
                int kb = ks * 16;
                unsigned a[4], bf[9][2];
                a[0] = *reinterpret_cast<unsigned*>(&Qs[(gm + lg) * FQW + kb + 2*lt]);
                a[1] = *reinterpret_cast<unsigned*>(&Qs[(gm + 8 + lg) * FQW + kb + 2*lt]);
                a[2] = *reinterpret_cast<unsigned*>(&Qs[(gm + lg) * FQW + kb + 2*lt + 8]);
                a[3] = *reinterpret_cast<unsigned*>(&Qs[(gm + 8 + lg) * FQW + kb + 2*lt + 8]);
                #pragma unroll
                for (int nt = 0; nt < 9; nt++) {
                    int cn = gc0 + nt * 8 + lg;
                    bf[nt][0] = *reinterpret_cast<unsigned*>(&Kp[cn * FQW + kb + 2*lt]);
                    bf[nt][1] = *reinterpret_cast<unsigned*>(&Kp[cn * FQW + kb + 2*lt + 8]);
                }
                #pragma unroll
                for (int nt = 0; nt < 9; nt++)
                    mmaf16(gg[nt], a, bf[nt]);
            }
            #pragma unroll
            for (int nt = 0; nt < 9; nt++) {
                int col = gc0 + nt * 8 + 2 * lt;
                *reinterpret_cast<float2*>(&Gs[(gm + lg) * GW + col]) =
                    make_float2(gg[nt][0], gg[nt][1]);
                *reinterpret_cast<float2*>(&Gs[(gm + 8 + lg) * GW + col]) =
                    make_float2(gg[nt][2], gg[nt][3]);
            }
        }

        // --- S = Q K^T ---
        float s_[2][4][4];
        #pragma unroll
        for (int mt = 0; mt < 2; mt++)
            #pragma unroll
            for (int nt = 0; nt < 4; nt++)
                #pragma unroll
                for (int q = 0; q < 4; q++) s_[mt][nt][q] = 0.f;
        #pragma unroll
        for (int ks = 0; ks < 8; ks++) {
            int kb = ks * 16;
            unsigned a[2][4], bf[4][2];
            #pragma unroll
            for (int mt = 0; mt < 2; mt++) {
                int r = wm0 + mt * 16 + lg;
                a[mt][0] = *reinterpret_cast<unsigned*>(&Qs[r * FQW + kb + 2*lt]);
                a[mt][1] = *reinterpret_cast<unsigned*>(&Qs[(r + 8) * FQW + kb + 2*lt]);
                a[mt][2] = *reinterpret_cast<unsigned*>(&Qs[r * FQW + kb + 2*lt + 8]);
                a[mt][3] = *reinterpret_cast<unsigned*>(&Qs[(r + 8) * FQW + kb + 2*lt + 8]);
            }
            #pragma unroll
            for (int nt = 0; nt < 4; nt++) {
                int cn = wn0 + nt * 8 + lg;
                bf[nt][0] = *reinterpret_cast<unsigned*>(&Kt[cn * FQW + kb + 2*lt]);
                bf[nt][1] = *reinterpret_cast<unsigned*>(&Kt[cn * FQW + kb + 2*lt + 8]);
            }
            #pragma unroll
            for (int mt = 0; mt < 2; mt++)
                #pragma unroll
                for (int nt = 0; nt < 4; nt++)
                    mmaf16(s_[mt][nt], a[mt], bf[nt]);
        }
        __syncthreads();   // Gs complete; Kt/Kp consumed

        // prefetch next iteration's Kt + Kp; overlaps with softmax + PV below
        if (kt + 1 < 8) prefetchKKp(kt + 1);

        // band add: S[i,j] += G[i, j-i+63]
        #pragma unroll
        for (int mt = 0; mt < 2; mt++) {
            #pragma unroll
            for (int ri = 0; ri < 2; ri++) {
                int i = wm0 + mt * 16 + lg + ri * 8;
                const float* grow = Gs + (size_t)i * GW - i + 63;
                #pragma unroll
                for (int nt = 0; nt < 4; nt++) {
                    int j = wn0 + nt * 8 + 2 * lt;
                    s_[mt][nt][ri * 2 + 0] += grow[j];
                    s_[mt][nt][ri * 2 + 1] += grow[j + 1];
                }
            }
        }

        // row max
        #pragma unroll
        for (int mt = 0; mt < 2; mt++) {
            #pragma unroll
            for (int ri = 0; ri < 2; ri++) {
                float v = -1e30f;
                #pragma unroll
                for (int nt = 0; nt < 4; nt++)
                    v = fmaxf(v, fmaxf(s_[mt][nt][ri * 2], s_[mt][nt][ri * 2 + 1]));
                v = fmaxf(v, __shfl_xor_sync(0xffffffff, v, 1));
                v = fmaxf(v, __shfl_xor_sync(0xffffffff, v, 2));
                if (lt == 0) {
                    int rl = wm0 + mt * 16 + lg + ri * 8;
                    redm[rl * 4 + (wid >> 1)] = v;
                }
            }
        }
        __syncthreads();

        float scl[2][2];
        #pragma unroll
        for (int mt = 0; mt < 2; mt++) {
            #pragma unroll
            for (int ri = 0; ri < 2; ri++) {
                int rl = wm0 + mt * 16 + lg + ri * 8;
                float v = fmaxf(fmaxf(redm[rl * 4 + 0], redm[rl * 4 + 1]),
                                fmaxf(redm[rl * 4 + 2], redm[rl * 4 + 3]));
                float mnew = fmaxf(mrow[mt][ri], v);
                scl[mt][ri] = expf(mrow[mt][ri] - mnew);
                mrow[mt][ri] = mnew;
            }
        }

        #pragma unroll
        for (int mt = 0; mt < 2; mt++) {
            #pragma unroll
            for (int ri = 0; ri < 2; ri++) {
                float m = mrow[mt][ri];
                float sum = 0.f;
                int r = wm0 + mt * 16 + lg + ri * 8;
                #pragma unroll
                for (int nt = 0; nt < 4; nt++) {
                    float e0 = expf(s_[mt][nt][ri * 2 + 0] - m);
                    float e1 = expf(s_[mt][nt][ri * 2 + 1] - m);
                    sum += e0 + e1;
                    int c0 = wn0 + nt * 8 + 2 * lt;
                    *reinterpret_cast<unsigned*>(&Ps[r * FQW + c0]) = pk2(e0, e1);
                    o[mt][nt][ri * 2 + 0] *= scl[mt][ri];
                    o[mt][nt][ri * 2 + 1] *= scl[mt][ri];
                }
                sum += __shfl_xor_sync(0xffffffff, sum, 1);
                sum += __shfl_xor_sync(0xffffffff, sum, 2);
                if (lt == 0) reds[r * 4 + (wid >> 1)] = sum;
            }
        }
        __syncthreads();

        #pragma unroll
        for (int mt = 0; mt < 2; mt++) {
            #pragma unroll
            for (int ri = 0; ri < 2; ri++) {
                int rl = wm0 + mt * 16 + lg + ri * 8;
                float ltile = reds[rl * 4 + 0] + reds[rl * 4 + 1]
                            + reds[rl * 4 + 2] + reds[rl * 4 + 3];
                lrow[mt][ri] = lrow[mt][ri] * scl[mt][ri] + ltile;
            }
        }

        // O += P @ V
        #pragma unroll
        for (int ks = 0; ks < 8; ks++) {
            int kb = ks * 16;
            unsigned a[2][4], bf[4][2];
            #pragma unroll
            for (int mt = 0; mt < 2; mt++) {
                int r = wm0 + mt * 16 + lg;
                a[mt][0] = *reinterpret_cast<unsigned*>(&Ps[r * FQW + kb + 2*lt]);
                a[mt][1] = *reinterpret_cast<unsigned*>(&Ps[(r + 8) * FQW + kb + 2*lt]);
                a[mt][2] = *reinterpret_cast<unsigned*>(&Ps[r * FQW + kb + 2*lt + 8]);
                a[mt][3] = *reinterpret_cast<unsigned*>(&Ps[(r + 8) * FQW + kb + 2*lt + 8]);
            }
            #pragma unroll
            for (int nt = 0; nt < 4; nt++) {
                int col = wn0 + nt * 8 + lg;
                bf[nt][0] = Vt2[(kb/2 + lt) * FQW + col];
                bf[nt][1] = Vt2[(kb/2 + lt + 4) * FQW + col];
            }
            #pragma unroll
            for (int mt = 0; mt < 2; mt++)
                #pragma unroll
                for (int nt = 0; nt < 4; nt++)
                    mmaf16(o[mt][nt], a[mt], bf[nt]);
        }
        __syncthreads();   // Ps, Vt2 consumed
    }

    // epilogue: normalize, gate, write fp16 rows to g_r[(token*NH+h)]
    #pragma unroll
    for (int mt = 0; mt < 2; mt++) {
        #pragma unroll
        for (int ri = 0; ri < 2; ri++) {
            int sglob = s0 + wm0 + mt * 16 + lg + ri * 8;
            int token = b * SS + sglob;
            float g = g_selval[token * NH + h];
            float inv = g / lrow[mt][ri];
            unsigned* rrow = g_r + ((size_t)token * NH + h) * 64;
            #pragma unroll
            for (int nt = 0; nt < 4; nt++) {
                int c0 = wn0 + nt * 8 + 2 * lt;
                rrow[c0 >> 1] = pk2(o[mt][nt][ri * 2 + 0] * inv,
                                    o[mt][nt][ri * 2 + 1] * inv);
            }
        }
    }
}

// ---------------- sel = curr @ sel_dst^T, top-8, sigmoid --------------------
__global__ void sel_topk_kernel(const float* __restrict__ curr,
                                const float* __restrict__ sdst)
{
    __shared__ float srow[IN];
    __shared__ float wsum[NE][4];
    __shared__ float vals[NE];
    int bs = blockIdx.x;
    int tid = threadIdx.x;
    const float* row = curr + (long)bs * IN;
    for (int i = tid; i < IN; i += 128) srow[i] = row[i];
    __syncthreads();

    float acc[NE];
    #pragma unroll
    for (int e = 0; e < NE; e++) acc[e] = 0.f;
    for (int i = tid; i < IN; i += 128) {
        float c = srow[i];
        #pragma unroll
        for (int e = 0; e < NE; e++)
            acc[e] = fmaf(c, sdst[e*IN + i], acc[e]);
    }
    int lane = tid & 31, w = tid >> 5;
    #pragma unroll
    for (int e = 0; e < NE; e++) {
        float v = acc[e];
        #pragma unroll
        for (int o = 16; o > 0; o >>= 1) v += __shfl_xor_sync(0xffffffff, v, o);
        if (lane == 0) wsum[e][w] = v;
    }
    __syncthreads();
    if (tid < NE) vals[tid] = wsum[tid][0] + wsum[tid][1] + wsum[tid][2] + wsum[tid][3];
    __syncthreads();
    if (tid == 0) {
        bool used[NE];
        #pragma unroll
        for (int e = 0; e < NE; e++) used[e] = false;
        for (int h = 0; h < NH; h++) {
            int bi = 0; float bv = -3.4e38f;
            for (int e = 0; e < NE; e++)
                if (!used[e] && vals[e] > bv) { bv = vals[e]; bi = e; }
            used[bi] = true;
            g_selidx[bs*NH + h] = bi;
            g_selval[bs*NH + h] = 1.f / (1.f + expf(-bv));
        }
    }
}

// ---------------- sinusoidal embedding --------------------------------------
__global__ void pemb_kernel()
{
    int i = blockIdx.x;
    int tid = threadIdx.x;
    float pos = (float)i - (float)(SS - 1);
    float cst = -logf(10000.f) / (float)IN;
    for (int j = tid; j < IN/2; j += 256) {
        float dv = expf((float)(2*j) * cst);
        float s, co;
        sincosf(pos * dv, &s, &co);
        g_pemb[(long)i*IN + 2*j]     = s;
        g_pemb[(long)i*IN + 2*j + 1] = co;
    }
}

// ---------------- launch ----------------------------------------------------
static char* symc(const void* sym) { void* p = nullptr; cudaGetSymbolAddress(&p, sym); return (char*)p; }

extern "C" void kernel_launch(void* const* d_in, const int* in_sizes, int n_in,
                              void* d_out, int out_size)
{
    const float* curr  = (const float*)d_in[0];
    const float* attn  = (const float*)d_in[1];
    const float* dtq   = (const float*)d_in[2];
    const float* dtkv  = (const float*)d_in[3];
    const float* oproj = (const float*)d_in[4];
    const float* ptpk  = (const float*)d_in[5];
    const float* sdst  = (const float*)d_in[6];
    const float* scale = (const float*)d_in[7];
    float* out = (float*)d_out;

    float* p_pemb   = (float*)symc(g_pemb);
    char*  p_cnt    = symc(g_cnt);
    char*  p_kpos_h = symc(g_kpos_h);

    static int init_done = 0;
    static cudaStream_t s1, s2;
    static cudaEvent_t evRoot, ev1, ev2;
    const int FLASH_SMEM = (64*FQW + 64*FQW + 128*FQW + 192*FQW)*2
                         + 64*FQW*4
                         + 64*GW*4 + 512*4;
    const int OB_SMEM = 2*128*FQW*2 + 128*4;
    if (!init_done) {
        cudaFuncSetAttribute(flash_kernel,
            cudaFuncAttributeMaxDynamicSharedMemorySize, FLASH_SMEM);
        cudaFuncSetAttribute(tgemm<0>,
            cudaFuncAttributeMaxDynamicSharedMemorySize, TG_SMEM);
        cudaFuncSetAttribute(tgemm<1>,
            cudaFuncAttributeMaxDynamicSharedMemorySize, TG_SMEM);
        cudaFuncSetAttribute(qexp_kernel,
            cudaFuncAttributeMaxDynamicSharedMemorySize, QX_SMEM);
        cudaFuncSetAttribute(obucket_kernel,
            cudaFuncAttributeMaxDynamicSharedMemorySize, OB_SMEM);
        cudaStreamCreateWithFlags(&s1, cudaStreamNonBlocking);
        cudaStreamCreateWithFlags(&s2, cudaStreamNonBlocking);
        cudaEventCreateWithFlags(&evRoot, cudaEventDisableTiming);
        cudaEventCreateWithFlags(&ev1, cudaEventDisableTiming);
        cudaEventCreateWithFlags(&ev2, cudaEventDisableTiming);
        init_done = 1;
    }

    // fork
    cudaEventRecord(evRoot, 0);
    cudaStreamWaitEvent(s1, evRoot, 0);
    cudaStreamWaitEvent(s2, evRoot, 0);

    // s1: expert selection + buckets + q projection
    cudaMemsetAsync(p_cnt, 0, NE * sizeof(int), s1);
    sel_topk_kernel<<<BT, 128, 0, s1>>>(curr, sdst);
    qbucket_kernel<<<(BT*NH + 255)/256, 256, 0, s1>>>();
    qexp_kernel<<<dim3(1, 32, NE), 256, QX_SMEM, s1>>>(curr, dtq, scale);
    cudaEventRecord(ev1, s1);

    // s2: positional embedding + kpos + kv
    pemb_kernel<<<RLEN, 256, 0, s2>>>();
    cudaMemsetAsync(p_kpos_h + (size_t)RLEN * 64 * 4, 0, 64 * 4, s2);
    tgemm<1><<<dim3(1, 16, 1), 256, TG_SMEM, s2>>>(p_pemb, ptpk, nullptr,
        RLEN, PROJ, IN, IN, IN, PROJ, scale, 3);
    tgemm<0><<<dim3(2, 32, 1), 256, TG_SMEM, s2>>>(attn, dtkv, nullptr,
        BT, 2*PROJ, IN, IN, 2*PROJ, 2*PROJ, scale, 2);
    cudaEventRecord(ev2, s2);

    // default: zero out while producers run, then join
    cudaMemsetAsync(out, 0, (size_t)BT * OUT * sizeof(float));
    cudaStreamWaitEvent(0, ev1, 0);
    cudaStreamWaitEvent(0, ev2, 0);

    // fused attention
    flash_kernel<<<dim3(16, BB*NH), 256, FLASH_SMEM>>>();

    // bucketed output projection (atomic accumulate over heads)
    obucket_kernel<<<dim3(8, 32, NE), 256, OB_SMEM>>>(oproj, out);
}

// round 14
// speedup vs baseline: 1.0445x; 1.0445x over previous
#include <cuda_runtime.h>
#include <cuda_fp16.h>
#include <math.h>

#define BB 4
#define SS 1024
#define IN 1024
#define OUT 1024
#define NH 8
#define NE 16
#define PROJ 128
#define BT (BB*SS)
#define RLEN (2*SS-1)

// ---------------- scratch ----------------------------------------------------
__device__ float    g_selval[BT*NH];
__device__ int      g_selidx[BT*NH];
__device__ int      g_cnt[NE];
__device__ int      g_list[NE*BT];
__device__ unsigned g_kh  [(size_t)BT*64];             // K * sc, fp16x2
__device__ unsigned g_vh  [(size_t)BT*64];             // V, fp16x2
__device__ float    g_pemb[(size_t)RLEN*IN];
__device__ unsigned g_kpos_h[(size_t)(RLEN+1)*64];     // kpos * sc, fp16x2 (+pad row)
__device__ unsigned g_qh  [(size_t)BB*NH*SS*64];       // Q * sc, fp16x2
__device__ unsigned g_r   [(size_t)BT*NH*64];          // gated attn out, fp16x2
__device__ half     g_oTh [(size_t)NE*OUT*PROJ];       // oproj^T fp16 [e][n][k]

// ---------------- fp16 helpers ----------------------------------------------
__device__ __forceinline__ unsigned pk2(float x, float y) {
    __half2 h = __floats2half2_rn(x, y);
    return *reinterpret_cast<unsigned*>(&h);
}
__device__ __forceinline__ void mmaf16(float c[4], const unsigned a[4],
                                       const unsigned b[2]) {
    asm volatile(
        "mma.sync.aligned.m16n8k16.row.col.f32.f16.f16.f32 "
        "{%0,%1,%2,%3},{%4,%5,%6,%7},{%8,%9},{%0,%1,%2,%3};"
        : "+f"(c[0]), "+f"(c[1]), "+f"(c[2]), "+f"(c[3])
        : "r"(a[0]), "r"(a[1]), "r"(a[2]), "r"(a[3]),
          "r"(b[0]), "r"(b[1]));
}

// tile geometry for generic GEMM
#define TW 40
#define STG_H (128*TW)
#define TG_SMEM (4*STG_H*2)
#define QX_SMEM (TG_SMEM + 128*4)

// ---------------- fp16 tensor GEMM, double-buffered ------------------------
// TRANSB=0: B row-major KxN. TRANSB=1: B row-major NxK (A @ B^T).
// alphaMode: 0 plain fp32 C, 2 split-kv fp16 epilogue (k*sc | v),
//            3 kpos fp16 epilogue (*sqrt(scale) -> g_kpos_h)
template<int TRANSB>
__global__ __launch_bounds__(256, 2)
void tgemm(const float* __restrict__ A, const float* __restrict__ Bm,
           float* __restrict__ C,
           int M, int N, int K, int lda, int ldb, int ldc,
           const float* __restrict__ scalep, int alphaMode)
{
    extern __shared__ half hsm[];
    half* AsBase = hsm;
    half* BsBase = hsm + 2*STG_H;

    const float* Ap = A;
    const float* Bp = Bm;
    float*       Cp = C;
    int m0 = blockIdx.y * 128;
    int n0 = blockIdx.x * 128;

    int tid  = threadIdx.x;
    int wid  = tid >> 5, lane = tid & 31;
    int wm0  = (wid & 1) * 64;
    int wn0  = (wid >> 1) * 32;
    int lg   = lane >> 2;
    int lt   = lane & 3;

    float c[4][4][4];
    #pragma unroll
    for (int i = 0; i < 4; i++)
        #pragma unroll
        for (int j = 0; j < 4; j++)
            #pragma unroll
            for (int q = 0; q < 4; q++) c[i][j][q] = 0.f;

    float4 ra[4];
    float4 rb4[4];
    float  cv[16];

    auto ldA = [&](int k0) {
        #pragma unroll
        for (int i = 0; i < 4; i++) {
            int m  = i * 32 + (tid >> 3);
            int kk = (tid & 7) * 4;
            ra[i] = make_float4(0.f, 0.f, 0.f, 0.f);
            if (m0 + m < M)
                ra[i] = *reinterpret_cast<const float4*>(Ap + (long)(m0 + m) * lda + k0 + kk);
        }
    };
    auto ldB = [&](int k0) {
        if (TRANSB == 0) {
            int n    = tid & 127;
            int kseg = (tid >> 7) * 16;
            const float* src = Bp + (long)(k0 + kseg) * ldb + n0 + n;
            #pragma unroll
            for (int j = 0; j < 16; j++) cv[j] = src[(long)j * ldb];
        } else {
            #pragma unroll
            for (int i = 0; i < 4; i++) {
                int nn = i * 32 + (tid >> 3);
                int kk = (tid & 7) * 4;
                rb4[i] = make_float4(0.f, 0.f, 0.f, 0.f);
                if (n0 + nn < N)
                    rb4[i] = *reinterpret_cast<const float4*>(Bp + (long)(n0 + nn) * ldb + k0 + kk);
            }
        }
    };
    auto stAB = [&](int buf) {
        half* As = AsBase + buf * STG_H;
        half* Bs = BsBase + buf * STG_H;
        #pragma unroll
        for (int i = 0; i < 4; i++) {
            int m  = i * 32 + (tid >> 3);
            int kk = (tid & 7) * 4;
            uint2 w;
            w.x = pk2(ra[i].x, ra[i].y);
            w.y = pk2(ra[i].z, ra[i].w);
            *reinterpret_cast<uint2*>(&As[m * TW + kk]) = w;
        }
        if (TRANSB == 0) {
            int n    = tid & 127;
            int kseg = (tid >> 7) * 16;
            #pragma unroll
            for (int j2 = 0; j2 < 4; j2++) {
                uint2 w;
                w.x = pk2(cv[j2*4+0], cv[j2*4+1]);
                w.y = pk2(cv[j2*4+2], cv[j2*4+3]);
                *reinterpret_cast<uint2*>(&Bs[n * TW + kseg + j2*4]) = w;
            }
        } else {
            #pragma unroll
            for (int i = 0; i < 4; i++) {
                int nn = i * 32 + (tid >> 3);
                int kk = (tid & 7) * 4;
                uint2 w;
                w.x = pk2(rb4[i].x, rb4[i].y);
                w.y = pk2(rb4[i].z, rb4[i].w);
                *reinterpret_cast<uint2*>(&Bs[nn * TW + kk]) = w;
            }
        }
    };
    auto domma = [&](int buf) {
        half* As = AsBase + buf * STG_H;
        half* Bs = BsBase + buf * STG_H;
        #pragma unroll
        for (int ks = 0; ks < 2; ks++) {
            int kb = ks * 16;
            unsigned a[4][4], b[4][2];
            #pragma unroll
            for (int mt = 0; mt < 4; mt++) {
                int r = wm0 + mt * 16 + lg;
                a[mt][0] = *reinterpret_cast<unsigned*>(&As[r * TW + kb + 2*lt]);
                a[mt][1] = *reinterpret_cast<unsigned*>(&As[(r + 8) * TW + kb + 2*lt]);
                a[mt][2] = *reinterpret_cast<unsigned*>(&As[r * TW + kb + 2*lt + 8]);
                a[mt][3] = *reinterpret_cast<unsigned*>(&As[(r + 8) * TW + kb + 2*lt + 8]);
            }
            #pragma unroll
            for (int nt = 0; nt < 4; nt++) {
                int cn = wn0 + nt * 8 + lg;
                b[nt][0] = *reinterpret_cast<unsigned*>(&Bs[cn * TW + kb + 2*lt]);
                b[nt][1] = *reinterpret_cast<unsigned*>(&Bs[cn * TW + kb + 2*lt + 8]);
            }
            #pragma unroll
            for (int mt = 0; mt < 4; mt++)
                #pragma unroll
                for (int nt = 0; nt < 4; nt++)
                    mmaf16(c[mt][nt], a[mt], b[nt]);
        }
    };

    int nk = K / 32;
    ldA(0); ldB(0);
    stAB(0);
    __syncthreads();
    for (int ki = 0; ki < nk; ki++) {
        if (ki + 1 < nk) { ldA((ki + 1) * 32); ldB((ki + 1) * 32); }
        domma(ki & 1);
        if (ki + 1 < nk) {
            stAB((ki + 1) & 1);
            __syncthreads();
        }
    }

    if (alphaMode == 2) {
        float sc = sqrtf(scalep[0]);
        #pragma unroll
        for (int mt = 0; mt < 4; mt++) {
            #pragma unroll
            for (int nt = 0; nt < 4; nt++) {
                #pragma unroll
                for (int ri = 0; ri < 2; ri++) {
                    int r  = m0 + wm0 + mt * 16 + lg + ri * 8;
                    int cc = n0 + wn0 + nt * 8 + 2 * lt;
                    float v0 = c[mt][nt][ri * 2 + 0];
                    float v1 = c[mt][nt][ri * 2 + 1];
                    if (cc < PROJ)
                        g_kh[(size_t)r * 64 + (cc >> 1)] = pk2(sc * v0, sc * v1);
                    else
                        g_vh[(size_t)r * 64 + ((cc - PROJ) >> 1)] = pk2(v0, v1);
                }
            }
        }
        return;
    }
    if (alphaMode == 3) {
        float sc = sqrtf(scalep[0]);
        #pragma unroll
        for (int mt = 0; mt < 4; mt++) {
            #pragma unroll
            for (int ri = 0; ri < 2; ri++) {
                int r = m0 + wm0 + mt * 16 + lg + ri * 8;
                if (r >= M) continue;
                #pragma unroll
                for (int nt = 0; nt < 4; nt++) {
                    int cc = n0 + wn0 + nt * 8 + 2 * lt;
                    g_kpos_h[(size_t)r * 64 + (cc >> 1)] =
                        pk2(sc * c[mt][nt][ri * 2 + 0], sc * c[mt][nt][ri * 2 + 1]);
                }
            }
        }
        return;
    }

    #pragma unroll
    for (int mt = 0; mt < 4; mt++) {
        #pragma unroll
        for (int nt = 0; nt < 4; nt++) {
            int r  = m0 + wm0 + mt * 16 + lg;
            int cc = n0 + wn0 + nt * 8 + 2 * lt;
            if (r < M) {
                if (cc     < N) Cp[(long)r * ldc + cc]     = c[mt][nt][0];
                if (cc + 1 < N) Cp[(long)r * ldc + cc + 1] = c[mt][nt][1];
            }
            if (r + 8 < M) {
                if (cc     < N) Cp[(long)(r + 8) * ldc + cc]     = c[mt][nt][2];
                if (cc + 1 < N) Cp[(long)(r + 8) * ldc + cc + 1] = c[mt][nt][3];
            }
        }
    }
}

// ---------------- expert-bucketed q projection (fp16 MMA, fp16 out) ---------
__global__ __launch_bounds__(256, 2)
void qexp_kernel(const float* __restrict__ curr, const float* __restrict__ dtq,
                 const float* __restrict__ scalep)
{
    extern __shared__ half hsm[];
    half* AsBase = hsm;
    half* BsBase = hsm + 2*STG_H;
    int*  ent    = (int*)(hsm + 4*STG_H);

    int e   = blockIdx.z;
    int cnt = g_cnt[e];
    int t0  = blockIdx.y * 128;
    if (t0 >= cnt) return;

    int tid  = threadIdx.x;
    if (tid < 128)
        ent[tid] = (t0 + tid < cnt) ? g_list[e * BT + t0 + tid] : -1;
    __syncthreads();

    const float* Bp = dtq + (size_t)e * IN * PROJ;

    int wid  = tid >> 5, lane = tid & 31;
    int wm0  = (wid & 1) * 64;
    int wn0  = (wid >> 1) * 32;
    int lg   = lane >> 2;
    int lt   = lane & 3;

    int tok4[4];
    #pragma unroll
    for (int i = 0; i < 4; i++) {
        int m = i * 32 + (tid >> 3);
        int en = ent[m];
        tok4[i] = (en >= 0) ? (en >> 3) : -1;
    }

    float c[4][4][4];
    #pragma unroll
    for (int i = 0; i < 4; i++)
        #pragma unroll
        for (int j = 0; j < 4; j++)
            #pragma unroll
            for (int q = 0; q < 4; q++) c[i][j][q] = 0.f;

    float4 ra[4];
    float  cv[16];
    auto ldA = [&](int k0) {
        int kk = (tid & 7) * 4;
        #pragma unroll
        for (int i = 0; i < 4; i++) {
            ra[i] = make_float4(0.f, 0.f, 0.f, 0.f);
            if (tok4[i] >= 0)
                ra[i] = *reinterpret_cast<const float4*>(curr + (size_t)tok4[i] * IN + k0 + kk);
        }
    };
    auto ldB = [&](int k0) {
        int n    = tid & 127;
        int kseg = (tid >> 7) * 16;
        const float* src = Bp + (size_t)(k0 + kseg) * PROJ + n;
        #pragma unroll
        for (int j = 0; j < 16; j++) cv[j] = src[(size_t)j * PROJ];
    };
    auto stAB = [&](int buf) {
        half* As = AsBase + buf * STG_H;
        half* Bs = BsBase + buf * STG_H;
        int kk = (tid & 7) * 4;
        #pragma unroll
        for (int i = 0; i < 4; i++) {
            int m = i * 32 + (tid >> 3);
            uint2 w;
            w.x = pk2(ra[i].x, ra[i].y);
            w.y = pk2(ra[i].z, ra[i].w);
            *reinterpret_cast<uint2*>(&As[m * TW + kk]) = w;
        }
        int n    = tid & 127;
        int kseg = (tid >> 7) * 16;
        #pragma unroll
        for (int j2 = 0; j2 < 4; j2++) {
            uint2 w;
            w.x = pk2(cv[j2*4+0], cv[j2*4+1]);
            w.y = pk2(cv[j2*4+2], cv[j2*4+3]);
            *reinterpret_cast<uint2*>(&Bs[n * TW + kseg + j2*4]) = w;
        }
    };
    auto domma = [&](int buf) {
        half* As = AsBase + buf * STG_H;
        half* Bs = BsBase + buf * STG_H;
        #pragma unroll
        for (int ks = 0; ks < 2; ks++) {
            int kb = ks * 16;
            unsigned a[4][4], b[4][2];
            #pragma unroll
            for (int mt = 0; mt < 4; mt++) {
                int r = wm0 + mt * 16 + lg;
                a[mt][0] = *reinterpret_cast<unsigned*>(&As[r * TW + kb + 2*lt]);
                a[mt][1] = *reinterpret_cast<unsigned*>(&As[(r + 8) * TW + kb + 2*lt]);
                a[mt][2] = *reinterpret_cast<unsigned*>(&As[r * TW + kb + 2*lt + 8]);
                a[mt][3] = *reinterpret_cast<unsigned*>(&As[(r + 8) * TW + kb + 2*lt + 8]);
            }
            #pragma unroll
            for (int nt = 0; nt < 4; nt++) {
                int cn = wn0 + nt * 8 + lg;
                b[nt][0] = *reinterpret_cast<unsigned*>(&Bs[cn * TW + kb + 2*lt]);
                b[nt][1] = *reinterpret_cast<unsigned*>(&Bs[cn * TW + kb + 2*lt + 8]);
            }
            #pragma unroll
            for (int mt = 0; mt < 4; mt++)
                #pragma unroll
                for (int nt = 0; nt < 4; nt++)
                    mmaf16(c[mt][nt], a[mt], b[nt]);
        }
    };

    ldA(0); ldB(0);
    stAB(0);
    __syncthreads();
    for (int ki = 0; ki < 32; ki++) {
        if (ki + 1 < 32) { ldA((ki + 1) * 32); ldB((ki + 1) * 32); }
        domma(ki & 1);
        if (ki + 1 < 32) { stAB((ki + 1) & 1); __syncthreads(); }
    }

    float alpha = sqrtf(scalep[0]);
    #pragma unroll
    for (int mt = 0; mt < 4; mt++) {
        #pragma unroll
        for (int ri = 0; ri < 2; ri++) {
            int rl = wm0 + mt * 16 + lg + ri * 8;
            int en = ent[rl];
            if (en < 0) continue;
            int token = en >> 3, h = en & 7;
            int b = token >> 10, s = token & 1023;
            unsigned* dst = g_qh + ((size_t)((b * NH + h) * SS + s)) * 64;
            #pragma unroll
            for (int nt = 0; nt < 4; nt++) {
                int cc = wn0 + nt * 8 + 2 * lt;
                dst[cc >> 1] = pk2(alpha * c[mt][nt][ri * 2 + 0],
                                   alpha * c[mt][nt][ri * 2 + 1]);
            }
        }
    }
}

// ---------------- oproj transpose+convert: [e][k][n] f32 -> [e][n][k] f16 ---
__global__ __launch_bounds__(256)
void oconv_kernel(const float* __restrict__ oproj)
{
    __shared__ float sm[32][33];
    int e  = blockIdx.z;
    int k0 = blockIdx.y * 32;
    int n0 = blockIdx.x * 32;
    int t  = threadIdx.x;
    int tr = t >> 5, tc = t & 31;

    const float* src = oproj + (size_t)e * PROJ * OUT;
    #pragma unroll
    for (int i = 0; i < 4; i++) {
        int k = k0 + tr + i * 8;
        sm[tr + i * 8][tc] = src[(size_t)k * OUT + n0 + tc];
    }
    __syncthreads();
    half* dst = g_oTh + (size_t)e * OUT * PROJ;
    #pragma unroll
    for (int i = 0; i < 4; i++) {
        int n = n0 + tr + i * 8;
        dst[(size_t)n * PROJ + k0 + tc] = __float2half_rn(sm[tc][tr + i * 8]);
    }
}

// ---------------- bucketed output projection (fp16 MMA, atomic add) ---------
#define FQW 136
__global__ __launch_bounds__(256, 2)
void obucket_kernel(float* __restrict__ out)
{
    extern __shared__ half hsm[];
    half* As = hsm;                       // 128 x 136
    half* Bs = hsm + 128*FQW;             // 128 x 136
    int*  ent = (int*)(hsm + 2*128*FQW);

    int e   = blockIdx.z;
    int cnt = g_cnt[e];
    int t0  = blockIdx.y * 128;
    if (t0 >= cnt) return;
    int n0  = blockIdx.x * 128;

    int tid = threadIdx.x;
    if (tid < 128)
        ent[tid] = (t0 + tid < cnt) ? g_list[e * BT + t0 + tid] : -1;
    __syncthreads();

    // A: g_r rows (already fp16)
    #pragma unroll
    for (int it = 0; it < 8; it++) {
        int lin = it * 256 + tid;
        int r = lin >> 4, c4 = lin & 15;
        int en = ent[r];
        uint4 v = make_uint4(0, 0, 0, 0);
        if (en >= 0)
            v = reinterpret_cast<const uint4*>(g_r)[(size_t)en * 16 + c4];
        *reinterpret_cast<uint4*>(&As[r * FQW + c4 * 8]) = v;
    }
    // B: pre-transposed fp16 oproj^T[e][n0+n][k] -> direct uint4 copies
    {
        const uint4* src = reinterpret_cast<const uint4*>(
            g_oTh + ((size_t)e * OUT + n0) * PROJ);
        #pragma unroll
        for (int it = 0; it < 8; it++) {
            int lin = it * 256 + tid;
            int r = lin >> 4, c4 = lin & 15;
            *reinterpret_cast<uint4*>(&Bs[r * FQW + c4 * 8]) = src[r * 16 + c4];
        }
    }
    __syncthreads();

    int wid = tid >> 5, lane = tid & 31;
    int wm0 = (wid & 1) * 64;
    int wn0 = (wid >> 1) * 32;
    int lg  = lane >> 2;
    int lt  = lane & 3;

    float c[4][4][4];
    #pragma unroll
    for (int i = 0; i < 4; i++)
        #pragma unroll
        for (int j = 0; j < 4; j++)
            #pragma unroll
            for (int q = 0; q < 4; q++) c[i][j][q] = 0.f;

    #pragma unroll
    for (int ks = 0; ks < 8; ks++) {
        int kb = ks * 16;
        unsigned a[4][4], b[4][2];
        #pragma unroll
        for (int mt = 0; mt < 4; mt++) {
            int r = wm0 + mt * 16 + lg;
            a[mt][0] = *reinterpret_cast<unsigned*>(&As[r * FQW + kb + 2*lt]);
            a[mt][1] = *reinterpret_cast<unsigned*>(&As[(r + 8) * FQW + kb + 2*lt]);
            a[mt][2] = *reinterpret_cast<unsigned*>(&As[r * FQW + kb + 2*lt + 8]);
            a[mt][3] = *reinterpret_cast<unsigned*>(&As[(r + 8) * FQW + kb + 2*lt + 8]);
        }
        #pragma unroll
        for (int nt = 0; nt < 4; nt++) {
            int cn = wn0 + nt * 8 + lg;
            b[nt][0] = *reinterpret_cast<unsigned*>(&Bs[cn * FQW + kb + 2*lt]);
            b[nt][1] = *reinterpret_cast<unsigned*>(&Bs[cn * FQW + kb + 2*lt + 8]);
        }
        #pragma unroll
        for (int mt = 0; mt < 4; mt++)
            #pragma unroll
            for (int nt = 0; nt < 4; nt++)
                mmaf16(c[mt][nt], a[mt], b[nt]);
    }

    #pragma unroll
    for (int mt = 0; mt < 4; mt++) {
        #pragma unroll
        for (int ri = 0; ri < 2; ri++) {
            int rl = wm0 + mt * 16 + lg + ri * 8;
            int en = ent[rl];
            if (en < 0) continue;
            int token = en >> 3;
            float* orow = out + (size_t)token * OUT;
            #pragma unroll
            for (int nt = 0; nt < 4; nt++) {
                int cc = n0 + wn0 + nt * 8 + 2 * lt;
                atomicAdd(&orow[cc],     c[mt][nt][ri * 2 + 0]);
                atomicAdd(&orow[cc + 1], c[mt][nt][ri * 2 + 1]);
            }
        }
    }
}

// ---------------- bucket build ----------------------------------------------
__global__ void qbucket_kernel()
{
    int i = blockIdx.x * 256 + threadIdx.x;
    if (i >= BT * NH) return;
    int e = g_selidx[i];
    int pos = atomicAdd(&g_cnt[e], 1);
    g_list[e * BT + pos] = i;
}

// ---------------- fused flash attention + relative-position band -------------
#define GW 198
__global__ __launch_bounds__(256)
void flash_kernel()
{
    extern __shared__ char smc[];
    half*     Qs   = (half*)smc;                        // 64 x 136
    half*     Ps   = Qs + 64*FQW;                       // 64 x 136
    half*     Kt   = Ps + 64*FQW;                       // 128 x 136
    half*     Kp   = Kt + 128*FQW;                      // 192 x 136 (kpos window)
    unsigned* Vt2  = (unsigned*)(Kp + 192*FQW);         // 64 x 136 (paired V)
    float*    Gs   = (float*)(Vt2 + 64*FQW);            // 64 x 198
    float*    redm = Gs + 64*GW;                        // 256
    float*    reds = redm + 256;                        // 256

    int zh = blockIdx.y;
    int b  = zh >> 3, h = zh & 7;
    int s0 = blockIdx.x * 64;
    int tid = threadIdx.x;
    int wid = tid >> 5, lane = tid & 31;
    int lg = lane >> 2, lt = lane & 3;
    int wm0 = (wid & 1) * 32;
    int wn0 = (wid >> 1) * 32;
    // G warp tiling: 16-row group + 9-tile half-window anchored at ws
    int gm = (wid & 3) * 16;
    int ws = 48 - gm;
    int ghalf = wid >> 2;
    int gc0 = ws + ghalf * 72;

    // Q tile 64x128 halves, direct fp16 copy
    {
        const uint4* qbase = reinterpret_cast<const uint4*>(g_qh + (size_t)(zh * SS + s0) * 64);
        #pragma unroll
        for (int it = 0; it < 4; it++) {
            int lin = it * 256 + tid;
            int r = lin >> 4, c4 = lin & 15;
            *reinterpret_cast<uint4*>(&Qs[r * FQW + c4 * 8]) = qbase[r * 16 + c4];
        }
    }

    float o[2][4][4];
    float mrow[2][2], lrow[2][2];
    #pragma unroll
    for (int mt = 0; mt < 2; mt++) {
        mrow[mt][0] = mrow[mt][1] = -1e30f;
        lrow[mt][0] = lrow[mt][1] = 0.f;
        #pragma unroll
        for (int nt = 0; nt < 4; nt++)
            #pragma unroll
            for (int q = 0; q < 4; q++) o[mt][nt][q] = 0.f;
    }

    for (int kt = 0; kt < 8; kt++) {
        int t0  = kt * 128;
        int bt0 = b * SS + t0;
        int base = t0 - s0 + 960;
        // K tile 128x128 halves, direct copy
        {
            const uint4* kbase = reinterpret_cast<const uint4*>(g_kh + (size_t)bt0 * 64);
            #pragma unroll
            for (int it = 0; it < 8; it++) {
                int lin = it * 256 + tid;
                int r = lin >> 4, c4 = lin & 15;
                *reinterpret_cast<uint4*>(&Kt[r * FQW + c4 * 8]) = kbase[r * 16 + c4];
            }
        }
        // V tile paired from fp16
        {
            const unsigned* vbase = g_vh + (size_t)bt0 * 64;
            #pragma unroll
            for (int it = 0; it < 8; it++) {
                int lin = it * 256 + tid;
                int tp = lin >> 5, p0 = (lin & 31) * 4;
                uint2 x = *reinterpret_cast<const uint2*>(vbase + (size_t)(2*tp) * 64 + (p0 >> 1));
                uint2 y = *reinterpret_cast<const uint2*>(vbase + (size_t)(2*tp + 1) * 64 + (p0 >> 1));
                uint4 w;
                w.x = __byte_perm(x.x, y.x, 0x5410);
                w.y = __byte_perm(x.x, y.x, 0x7632);
                w.z = __byte_perm(x.y, y.y, 0x5410);
                w.w = __byte_perm(x.y, y.y, 0x7632);
                *reinterpret_cast<uint4*>(&Vt2[tp * FQW + p0]) = w;
            }
        }
        // kpos window 192 rows (fp16, L2-resident)
        {
            const uint4* kp4 = reinterpret_cast<const uint4*>(g_kpos_h);
            #pragma unroll
            for (int it = 0; it < 12; it++) {
                int lin = it * 256 + tid;
                int w = lin >> 4, c4 = lin & 15;
                uint4 v = kp4[(size_t)(base + w) * 16 + c4];
                *reinterpret_cast<uint4*>(&Kp[w * FQW + c4 * 8]) = v;
            }
        }
        __syncthreads();

        // --- G = Q @ Kp^T, band-trimmed: 16 rows x 72 cols per warp ---
        {
            float gg[9][4];
            #pragma unroll
            for (int nt = 0; nt < 9; nt++)
                #pragma unroll
                for (int q = 0; q < 4; q++) gg[nt][q] = 0.f;
            #pragma unroll
            for (int ks = 0; ks < 8; ks++) {
                int kb = ks * 16;
                unsigned a[4], bf[9][2];
                a[0] = *reinterpret_cast<unsigned*>(&Qs[(gm + lg) * FQW + kb + 2*lt]);
                a[1] = *reinterpret_cast<unsigned*>(&Qs[(gm + 8 + lg) * FQW + kb + 2*lt]);
                a[2] = *reinterpret_cast<unsigned*>(&Qs[(gm + lg) * FQW + kb + 2*lt + 8]);
                a[3] = *reinterpret_cast<unsigned*>(&Qs[(gm + 8 + lg) * FQW + kb + 2*lt + 8]);
                #pragma unroll
                for (int nt = 0; nt < 9; nt++) {
                    int cn = gc0 + nt * 8 + lg;
                    bf[nt][0] = *reinterpret_cast<unsigned*>(&Kp[cn * FQW + kb + 2*lt]);
                    bf[nt][1] = *reinterpret_cast<unsigned*>(&Kp[cn * FQW + kb + 2*lt + 8]);
                }
                #pragma unroll
                for (int nt = 0; nt < 9; nt++)
                    mmaf16(gg[nt], a, bf[nt]);
            }
            #pragma unroll
            for (int nt = 0; nt < 9; nt++) {
                int col = gc0 + nt * 8 + 2 * lt;
                *reinterpret_cast<float2*>(&Gs[(gm + lg) * GW + col]) =
                    make_float2(gg[nt][0], gg[nt][1]);
                *reinterpret_cast<float2*>(&Gs[(gm + 8 + lg) * GW + col]) =
                    make_float2(gg[nt][2], gg[nt][3]);
            }
        }

        // --- S = Q K^T ---
        float s_[2][4][4];
        #pragma unroll
        for (int mt = 0; mt < 2; mt++)
            #pragma unroll
            for (int nt = 0; nt < 4; nt++)
                #pragma unroll
                for (int q = 0; q < 4; q++) s_[mt][nt][q] = 0.f;
        #pragma unroll
        for (int ks = 0; ks < 8; ks++) {
            int kb = ks * 16;
            unsigned a[2][4], bf[4][2];
            #pragma unroll
            for (int mt = 0; mt < 2; mt++) {
                int r = wm0 + mt * 16 + lg;
                a[mt][0] = *reinterpret_cast<unsigned*>(&Qs[r * FQW + kb + 2*lt]);
                a[mt][1] = *reinterpret_cast<unsigned*>(&Qs[(r + 8) * FQW + kb + 2*lt]);
                a[mt][2] = *reinterpret_cast<unsigned*>(&Qs[r * FQW + kb + 2*lt + 8]);
                a[mt][3] = *reinterpret_cast<unsigned*>(&Qs[(r + 8) * FQW + kb + 2*lt + 8]);
            }
            #pragma unroll
            for (int nt = 0; nt < 4; nt++) {
                int cn = wn0 + nt * 8 + lg;
                bf[nt][0] = *reinterpret_cast<unsigned*>(&Kt[cn * FQW + kb + 2*lt]);
                bf[nt][1] = *reinterpret_cast<unsigned*>(&Kt[cn * FQW + kb + 2*lt + 8]);
            }
            #pragma unroll
            for (int mt = 0; mt < 2; mt++)
                #pragma unroll
                for (int nt = 0; nt < 4; nt++)
                    mmaf16(s_[mt][nt], a[mt], bf[nt]);
        }
        __syncthreads();   // Gs complete

        // band add: S[i,j] += G[i, j-i+63]
        #pragma unroll
        for (int mt = 0; mt < 2; mt++) {
            #pragma unroll
            for (int ri = 0; ri < 2; ri++) {
                int i = wm0 + mt * 16 + lg + ri * 8;
                const float* grow = Gs + (size_t)i * GW - i + 63;
                #pragma unroll
                for (int nt = 0; nt < 4; nt++) {
                    int j = wn0 + nt * 8 + 2 * lt;
                    s_[mt][nt][ri * 2 + 0] += grow[j];
                    s_[mt][nt][ri * 2 + 1] += grow[j + 1];
                }
            }
        }

        // row max
        #pragma unroll
        for (int mt = 0; mt < 2; mt++) {
            #pragma unroll
            for (int ri = 0; ri < 2; ri++) {
                float v = -1e30f;
                #pragma unroll
                for (int nt = 0; nt < 4; nt++)
                    v = fmaxf(v, fmaxf(s_[mt][nt][ri * 2], s_[mt][nt][ri * 2 + 1]));
                v = fmaxf(v, __shfl_xor_sync(0xffffffff, v, 1));
                v = fmaxf(v, __shfl_xor_sync(0xffffffff, v, 2));
                if (lt == 0) {
                    int rl = wm0 + mt * 16 + lg + ri * 8;
                    redm[rl * 4 + (wid >> 1)] = v;
                }
            }
        }
        __syncthreads();

        float scl[2][2];
        #pragma unroll
        for (int mt = 0; mt < 2; mt++) {
            #pragma unroll
            for (int ri = 0; ri < 2; ri++) {
                int rl = wm0 + mt * 16 + lg + ri * 8;
                float v = fmaxf(fmaxf(redm[rl * 4 + 0], redm[rl * 4 + 1]),
                                fmaxf(redm[rl * 4 + 2], redm[rl * 4 + 3]));
                float mnew = fmaxf(mrow[mt][ri], v);
                scl[mt][ri] = expf(mrow[mt][ri] - mnew);
                mrow[mt][ri] = mnew;
            }
        }

        #pragma unroll
        for (int mt = 0; mt < 2; mt++) {
            #pragma unroll
            for (int ri = 0; ri < 2; ri++) {
                float m = mrow[mt][ri];
                float sum = 0.f;
                int r = wm0 + mt * 16 + lg + ri * 8;
                #pragma unroll
                for (int nt = 0; nt < 4; nt++) {
                    float e0 = expf(s_[mt][nt][ri * 2 + 0] - m);
                    float e1 = expf(s_[mt][nt][ri * 2 + 1] - m);
                    sum += e0 + e1;
                    int c0 = wn0 + nt * 8 + 2 * lt;
                    *reinterpret_cast<unsigned*>(&Ps[r * FQW + c0]) = pk2(e0, e1);
                    o[mt][nt][ri * 2 + 0] *= scl[mt][ri];
                    o[mt][nt][ri * 2 + 1] *= scl[mt][ri];
                }
                sum += __shfl_xor_sync(0xffffffff, sum, 1);
                sum += __shfl_xor_sync(0xffffffff, sum, 2);
                if (lt == 0) reds[r * 4 + (wid >> 1)] = sum;
            }
        }
        __syncthreads();

        #pragma unroll
        for (int mt = 0; mt < 2; mt++) {
            #pragma unroll
            for (int ri = 0; ri < 2; ri++) {
                int rl = wm0 + mt * 16 + lg + ri * 8;
                float ltile = reds[rl * 4 + 0] + reds[rl * 4 + 1]
                            + reds[rl * 4 + 2] + reds[rl * 4 + 3];
                lrow[mt][ri] = lrow[mt][ri] * scl[mt][ri] + ltile;
            }
        }

        // O += P @ V
        #pragma unroll
        for (int ks = 0; ks < 8; ks++) {
            int kb = ks * 16;
            unsigned a[2][4], bf[4][2];
            #pragma unroll
            for (int mt = 0; mt < 2; mt++) {
                int r = wm0 + mt * 16 + lg;
                a[mt][0] = *reinterpret_cast<unsigned*>(&Ps[r * FQW + kb + 2*lt]);
                a[mt][1] = *reinterpret_cast<unsigned*>(&Ps[(r + 8) * FQW + kb + 2*lt]);
                a[mt][2] = *reinterpret_cast<unsigned*>(&Ps[r * FQW + kb + 2*lt + 8]);
                a[mt][3] = *reinterpret_cast<unsigned*>(&Ps[(r + 8) * FQW + kb + 2*lt + 8]);
            }
            #pragma unroll
            for (int nt = 0; nt < 4; nt++) {
                int col = wn0 + nt * 8 + lg;
                bf[nt][0] = Vt2[(kb/2 + lt) * FQW + col];
                bf[nt][1] = Vt2[(kb/2 + lt + 4) * FQW + col];
            }
            #pragma unroll
            for (int mt = 0; mt < 2; mt++)
                #pragma unroll
                for (int nt = 0; nt < 4; nt++)
                    mmaf16(o[mt][nt], a[mt], bf[nt]);
        }
        __syncthreads();
    }

    // epilogue: normalize, gate, write fp16 rows to g_r[(token*NH+h)]
    #pragma unroll
    for (int mt = 0; mt < 2; mt++) {
        #pragma unroll
        for (int ri = 0; ri < 2; ri++) {
            int sglob = s0 + wm0 + mt * 16 + lg + ri * 8;
            int token = b * SS + sglob;
            float g = g_selval[token * NH + h];
            float inv = g / lrow[mt][ri];
            unsigned* rrow = g_r + ((size_t)token * NH + h) * 64;
            #pragma unroll
            for (int nt = 0; nt < 4; nt++) {
                int c0 = wn0 + nt * 8 + 2 * lt;
                rrow[c0 >> 1] = pk2(o[mt][nt][ri * 2 + 0] * inv,
                                    o[mt][nt][ri * 2 + 1] * inv);
            }
        }
    }
}

// ---------------- sel = curr @ sel_dst^T, top-8, sigmoid --------------------
__global__ void sel_topk_kernel(const float* __restrict__ curr,
                                const float* __restrict__ sdst)
{
    __shared__ float srow[IN];
    __shared__ float wsum[NE][4];
    __shared__ float vals[NE];
    int bs = blockIdx.x;
    int tid = threadIdx.x;
    const float* row = curr + (long)bs * IN;
    for (int i = tid; i < IN; i += 128) srow[i] = row[i];
    __syncthreads();

    float acc[NE];
    #pragma unroll
    for (int e = 0; e < NE; e++) acc[e] = 0.f;
    for (int i = tid; i < IN; i += 128) {
        float c = srow[i];
        #pragma unroll
        for (int e = 0; e < NE; e++)
            acc[e] = fmaf(c, sdst[e*IN + i], acc[e]);
    }
    int lane = tid & 31, w = tid >> 5;
    #pragma unroll
    for (int e = 0; e < NE; e++) {
        float v = acc[e];
        #pragma unroll
        for (int o = 16; o > 0; o >>= 1) v += __shfl_xor_sync(0xffffffff, v, o);
        if (lane == 0) wsum[e][w] = v;
    }
    __syncthreads();
    if (tid < NE) vals[tid] = wsum[tid][0] + wsum[tid][1] + wsum[tid][2] + wsum[tid][3];
    __syncthreads();
    if (tid == 0) {
        bool used[NE];
        #pragma unroll
        for (int e = 0; e < NE; e++) used[e] = false;
        for (int h = 0; h < NH; h++) {
            int bi = 0; float bv = -3.4e38f;
            for (int e = 0; e < NE; e++)
                if (!used[e] && vals[e] > bv) { bv = vals[e]; bi = e; }
            used[bi] = true;
            g_selidx[bs*NH + h] = bi;
            g_selval[bs*NH + h] = 1.f / (1.f + expf(-bv));
        }
    }
}

// ---------------- sinusoidal embedding --------------------------------------
__global__ void pemb_kernel()
{
    int i = blockIdx.x;
    int tid = threadIdx.x;
    float pos = (float)i - (float)(SS - 1);
    float cst = -logf(10000.f) / (float)IN;
    for (int j = tid; j < IN/2; j += 256) {
        float dv = expf((float)(2*j) * cst);
        float s, co;
        sincosf(pos * dv, &s, &co);
        g_pemb[(long)i*IN + 2*j]     = s;
        g_pemb[(long)i*IN + 2*j + 1] = co;
    }
}

// ---------------- launch ----------------------------------------------------
static char* symc(const void* sym) { void* p = nullptr; cudaGetSymbolAddress(&p, sym); return (char*)p; }

extern "C" void kernel_launch(void* const* d_in, const int* in_sizes, int n_in,
                              void* d_out, int out_size)
{
    const float* curr  = (const float*)d_in[0];
    const float* attn  = (const float*)d_in[1];
    const float* dtq   = (const float*)d_in[2];
    const float* dtkv  = (const float*)d_in[3];
    const float* oproj = (const float*)d_in[4];
    const float* ptpk  = (const float*)d_in[5];
    const float* sdst  = (const float*)d_in[6];
    const float* scale = (const float*)d_in[7];
    float* out = (float*)d_out;

    float* p_pemb   = (float*)symc(g_pemb);
    char*  p_cnt    = symc(g_cnt);
    char*  p_kpos_h = symc(g_kpos_h);

    static int init_done = 0;
    static cudaStream_t s1, s2;
    static cudaEvent_t evRoot, ev1, ev2;
    const int FLASH_SMEM = (64*FQW + 64*FQW + 128*FQW + 192*FQW)*2
                         + 64*FQW*4
                         + 64*GW*4 + 512*4;
    const int OB_SMEM = 2*128*FQW*2 + 128*4;
    if (!init_done) {
        cudaFuncSetAttribute(flash_kernel,
            cudaFuncAttributeMaxDynamicSharedMemorySize, FLASH_SMEM);
        cudaFuncSetAttribute(tgemm<0>,
            cudaFuncAttributeMaxDynamicSharedMemorySize, TG_SMEM);
        cudaFuncSetAttribute(tgemm<1>,
            cudaFuncAttributeMaxDynamicSharedMemorySize, TG_SMEM);
        cudaFuncSetAttribute(qexp_kernel,
            cudaFuncAttributeMaxDynamicSharedMemorySize, QX_SMEM);
        cudaFuncSetAttribute(obucket_kernel,
            cudaFuncAttributeMaxDynamicSharedMemorySize, OB_SMEM);
        cudaStreamCreateWithFlags(&s1, cudaStreamNonBlocking);
        cudaStreamCreateWithFlags(&s2, cudaStreamNonBlocking);
        cudaEventCreateWithFlags(&evRoot, cudaEventDisableTiming);
        cudaEventCreateWithFlags(&ev1, cudaEventDisableTiming);
        cudaEventCreateWithFlags(&ev2, cudaEventDisableTiming);
        init_done = 1;
    }

    // fork
    cudaEventRecord(evRoot, 0);
    cudaStreamWaitEvent(s1, evRoot, 0);
    cudaStreamWaitEvent(s2, evRoot, 0);

    // s1: expert selection + buckets + q projection
    cudaMemsetAsync(p_cnt, 0, NE * sizeof(int), s1);
    sel_topk_kernel<<<BT, 128, 0, s1>>>(curr, sdst);
    qbucket_kernel<<<(BT*NH + 255)/256, 256, 0, s1>>>();
    qexp_kernel<<<dim3(1, 32, NE), 256, QX_SMEM, s1>>>(curr, dtq, scale);
    cudaEventRecord(ev1, s1);

    // s2: positional embedding + kpos + kv
    pemb_kernel<<<RLEN, 256, 0, s2>>>();
    cudaMemsetAsync(p_kpos_h + (size_t)RLEN * 64 * 4, 0, 64 * 4, s2);
    tgemm<1><<<dim3(1, 16, 1), 256, TG_SMEM, s2>>>(p_pemb, ptpk, nullptr,
        RLEN, PROJ, IN, IN, IN, PROJ, scale, 3);
    tgemm<0><<<dim3(2, 32, 1), 256, TG_SMEM, s2>>>(attn, dtkv, nullptr,
        BT, 2*PROJ, IN, IN, 2*PROJ, 2*PROJ, scale, 2);
    cudaEventRecord(ev2, s2);

    // default: zero out + transpose oproj while producers run, then join
    cudaMemsetAsync(out, 0, (size_t)BT * OUT * sizeof(float));
    oconv_kernel<<<dim3(OUT/32, PROJ/32, NE), 256>>>(oproj);
    cudaStreamWaitEvent(0, ev1, 0);
    cudaStreamWaitEvent(0, ev2, 0);

    // fused attention
    flash_kernel<<<dim3(16, BB*NH), 256, FLASH_SMEM>>>();

    // bucketed output projection (atomic accumulate over heads)
    obucket_kernel<<<dim3(8, 32, NE), 256, OB_SMEM>>>(out);
}

// round 15
// speedup vs baseline: 1.0497x; 1.0050x over previous
#include <cuda_runtime.h>
#include <cuda_fp16.h>
#include <math.h>

#define BB 4
#define SS 1024
#define IN 1024
#define OUT 1024
#define NH 8
#define NE 16
#define PROJ 128
#define BT (BB*SS)
#define RLEN (2*SS-1)

// ---------------- scratch ----------------------------------------------------
__device__ float    g_selval[BT*NH];
__device__ int      g_selidx[BT*NH];
__device__ int      g_cnt[NE];
__device__ int      g_list[NE*BT];
__device__ unsigned g_kh  [(size_t)BT*64];             // K * sc, fp16x2
__device__ unsigned g_vh  [(size_t)BT*64];             // V, fp16x2
__device__ float    g_pemb[(size_t)RLEN*IN];
__device__ unsigned g_kpos_h[(size_t)(RLEN+1)*64];     // kpos * sc, fp16x2 (+pad row)
__device__ unsigned g_qh  [(size_t)BB*NH*SS*64];       // Q * sc, fp16x2
__device__ unsigned g_r   [(size_t)BT*NH*64];          // gated attn out, fp16x2
__device__ half     g_oTh [(size_t)NE*OUT*PROJ];       // oproj^T fp16 [e][n][k]

// ---------------- fp16 helpers ----------------------------------------------
__device__ __forceinline__ unsigned pk2(float x, float y) {
    __half2 h = __floats2half2_rn(x, y);
    return *reinterpret_cast<unsigned*>(&h);
}
__device__ __forceinline__ void mmaf16(float c[4], const unsigned a[4],
                                       const unsigned b[2]) {
    asm volatile(
        "mma.sync.aligned.m16n8k16.row.col.f32.f16.f16.f32 "
        "{%0,%1,%2,%3},{%4,%5,%6,%7},{%8,%9},{%0,%1,%2,%3};"
        : "+f"(c[0]), "+f"(c[1]), "+f"(c[2]), "+f"(c[3])
        : "r"(a[0]), "r"(a[1]), "r"(a[2]), "r"(a[3]),
          "r"(b[0]), "r"(b[1]));
}

// tile geometry for generic GEMM
#define TW 40
#define STG_H (128*TW)
#define TG_SMEM (4*STG_H*2)
#define QX_SMEM (TG_SMEM + 128*4)

// ---------------- fp16 tensor GEMM, double-buffered ------------------------
// TRANSB=0: B row-major KxN. TRANSB=1: B row-major NxK (A @ B^T).
// alphaMode: 0 plain fp32 C, 2 split-kv fp16 epilogue (k*sc | v),
//            3 kpos fp16 epilogue (*sqrt(scale) -> g_kpos_h)
template<int TRANSB>
__global__ __launch_bounds__(256, 2)
void tgemm(const float* __restrict__ A, const float* __restrict__ Bm,
           float* __restrict__ C,
           int M, int N, int K, int lda, int ldb, int ldc,
           const float* __restrict__ scalep, int alphaMode)
{
    extern __shared__ half hsm[];
    half* AsBase = hsm;
    half* BsBase = hsm + 2*STG_H;

    const float* Ap = A;
    const float* Bp = Bm;
    float*       Cp = C;
    int m0 = blockIdx.y * 128;
    int n0 = blockIdx.x * 128;

    int tid  = threadIdx.x;
    int wid  = tid >> 5, lane = tid & 31;
    int wm0  = (wid & 1) * 64;
    int wn0  = (wid >> 1) * 32;
    int lg   = lane >> 2;
    int lt   = lane & 3;

    float c[4][4][4];
    #pragma unroll
    for (int i = 0; i < 4; i++)
        #pragma unroll
        for (int j = 0; j < 4; j++)
            #pragma unroll
            for (int q = 0; q < 4; q++) c[i][j][q] = 0.f;

    float4 ra[4];
    float4 rb4[4];
    float  cv[16];

    auto ldA = [&](int k0) {
        #pragma unroll
        for (int i = 0; i < 4; i++) {
            int m  = i * 32 + (tid >> 3);
            int kk = (tid & 7) * 4;
            ra[i] = make_float4(0.f, 0.f, 0.f, 0.f);
            if (m0 + m < M)
                ra[i] = *reinterpret_cast<const float4*>(Ap + (long)(m0 + m) * lda + k0 + kk);
        }
    };
    auto ldB = [&](int k0) {
        if (TRANSB == 0) {
            int n    = tid & 127;
            int kseg = (tid >> 7) * 16;
            const float* src = Bp + (long)(k0 + kseg) * ldb + n0 + n;
            #pragma unroll
            for (int j = 0; j < 16; j++) cv[j] = src[(long)j * ldb];
        } else {
            #pragma unroll
            for (int i = 0; i < 4; i++) {
                int nn = i * 32 + (tid >> 3);
                int kk = (tid & 7) * 4;
                rb4[i] = make_float4(0.f, 0.f, 0.f, 0.f);
                if (n0 + nn < N)
                    rb4[i] = *reinterpret_cast<const float4*>(Bp + (long)(n0 + nn) * ldb + k0 + kk);
            }
        }
    };
    auto stAB = [&](int buf) {
        half* As = AsBase + buf * STG_H;
        half* Bs = BsBase + buf * STG_H;
        #pragma unroll
        for (int i = 0; i < 4; i++) {
            int m  = i * 32 + (tid >> 3);
            int kk = (tid & 7) * 4;
            uint2 w;
            w.x = pk2(ra[i].x, ra[i].y);
            w.y = pk2(ra[i].z, ra[i].w);
            *reinterpret_cast<uint2*>(&As[m * TW + kk]) = w;
        }
        if (TRANSB == 0) {
            int n    = tid & 127;
            int kseg = (tid >> 7) * 16;
            #pragma unroll
            for (int j2 = 0; j2 < 4; j2++) {
                uint2 w;
                w.x = pk2(cv[j2*4+0], cv[j2*4+1]);
                w.y = pk2(cv[j2*4+2], cv[j2*4+3]);
                *reinterpret_cast<uint2*>(&Bs[n * TW + kseg + j2*4]) = w;
            }
        } else {
            #pragma unroll
            for (int i = 0; i < 4; i++) {
                int nn = i * 32 + (tid >> 3);
                int kk = (tid & 7) * 4;
                uint2 w;
                w.x = pk2(rb4[i].x, rb4[i].y);
                w.y = pk2(rb4[i].z, rb4[i].w);
                *reinterpret_cast<uint2*>(&Bs[nn * TW + kk]) = w;
            }
        }
    };
    auto domma = [&](int buf) {
        half* As = AsBase + buf * STG_H;
        half* Bs = BsBase + buf * STG_H;
        #pragma unroll
        for (int ks = 0; ks < 2; ks++) {
            int kb = ks * 16;
            unsigned a[4][4], b[4][2];
            #pragma unroll
            for (int mt = 0; mt < 4; mt++) {
                int r = wm0 + mt * 16 + lg;
                a[mt][0] = *reinterpret_cast<unsigned*>(&As[r * TW + kb + 2*lt]);
                a[mt][1] = *reinterpret_cast<unsigned*>(&As[(r + 8) * TW + kb + 2*lt]);
                a[mt][2] = *reinterpret_cast<unsigned*>(&As[r * TW + kb + 2*lt + 8]);
                a[mt][3] = *reinterpret_cast<unsigned*>(&As[(r + 8) * TW + kb + 2*lt + 8]);
            }
            #pragma unroll
            for (int nt = 0; nt < 4; nt++) {
                int cn = wn0 + nt * 8 + lg;
                b[nt][0] = *reinterpret_cast<unsigned*>(&Bs[cn * TW + kb + 2*lt]);
                b[nt][1] = *reinterpret_cast<unsigned*>(&Bs[cn * TW + kb + 2*lt + 8]);
            }
            #pragma unroll
            for (int mt = 0; mt < 4; mt++)
                #pragma unroll
                for (int nt = 0; nt < 4; nt++)
                    mmaf16(c[mt][nt], a[mt], b[nt]);
        }
    };

    int nk = K / 32;
    ldA(0); ldB(0);
    stAB(0);
    __syncthreads();
    for (int ki = 0; ki < nk; ki++) {
        if (ki + 1 < nk) { ldA((ki + 1) * 32); ldB((ki + 1) * 32); }
        domma(ki & 1);
        if (ki + 1 < nk) {
            stAB((ki + 1) & 1);
            __syncthreads();
        }
    }

    if (alphaMode == 2) {
        float sc = sqrtf(scalep[0]);
        #pragma unroll
        for (int mt = 0; mt < 4; mt++) {
            #pragma unroll
            for (int nt = 0; nt < 4; nt++) {
                #pragma unroll
                for (int ri = 0; ri < 2; ri++) {
                    int r  = m0 + wm0 + mt * 16 + lg + ri * 8;
                    int cc = n0 + wn0 + nt * 8 + 2 * lt;
                    float v0 = c[mt][nt][ri * 2 + 0];
                    float v1 = c[mt][nt][ri * 2 + 1];
                    if (cc < PROJ)
                        g_kh[(size_t)r * 64 + (cc >> 1)] = pk2(sc * v0, sc * v1);
                    else
                        g_vh[(size_t)r * 64 + ((cc - PROJ) >> 1)] = pk2(v0, v1);
                }
            }
        }
        return;
    }
    if (alphaMode == 3) {
        float sc = sqrtf(scalep[0]);
        #pragma unroll
        for (int mt = 0; mt < 4; mt++) {
            #pragma unroll
            for (int ri = 0; ri < 2; ri++) {
                int r = m0 + wm0 + mt * 16 + lg + ri * 8;
                if (r >= M) continue;
                #pragma unroll
                for (int nt = 0; nt < 4; nt++) {
                    int cc = n0 + wn0 + nt * 8 + 2 * lt;
                    g_kpos_h[(size_t)r * 64 + (cc >> 1)] =
                        pk2(sc * c[mt][nt][ri * 2 + 0], sc * c[mt][nt][ri * 2 + 1]);
                }
            }
        }
        return;
    }

    #pragma unroll
    for (int mt = 0; mt < 4; mt++) {
        #pragma unroll
        for (int nt = 0; nt < 4; nt++) {
            int r  = m0 + wm0 + mt * 16 + lg;
            int cc = n0 + wn0 + nt * 8 + 2 * lt;
            if (r < M) {
                if (cc     < N) Cp[(long)r * ldc + cc]     = c[mt][nt][0];
                if (cc + 1 < N) Cp[(long)r * ldc + cc + 1] = c[mt][nt][1];
            }
            if (r + 8 < M) {
                if (cc     < N) Cp[(long)(r + 8) * ldc + cc]     = c[mt][nt][2];
                if (cc + 1 < N) Cp[(long)(r + 8) * ldc + cc + 1] = c[mt][nt][3];
            }
        }
    }
}

// ---------------- expert-bucketed q projection (fp16 MMA, fp16 out) ---------
__global__ __launch_bounds__(256, 2)
void qexp_kernel(const float* __restrict__ curr, const float* __restrict__ dtq,
                 const float* __restrict__ scalep)
{
    extern __shared__ half hsm[];
    half* AsBase = hsm;
    half* BsBase = hsm + 2*STG_H;
    int*  ent    = (int*)(hsm + 4*STG_H);

    int e   = blockIdx.z;
    int cnt = g_cnt[e];
    int t0  = blockIdx.y * 128;
    if (t0 >= cnt) return;

    int tid  = threadIdx.x;
    if (tid < 128)
        ent[tid] = (t0 + tid < cnt) ? g_list[e * BT + t0 + tid] : -1;
    __syncthreads();

    const float* Bp = dtq + (size_t)e * IN * PROJ;

    int wid  = tid >> 5, lane = tid & 31;
    int wm0  = (wid & 1) * 64;
    int wn0  = (wid >> 1) * 32;
    int lg   = lane >> 2;
    int lt   = lane & 3;

    int tok4[4];
    #pragma unroll
    for (int i = 0; i < 4; i++) {
        int m = i * 32 + (tid >> 3);
        int en = ent[m];
        tok4[i] = (en >= 0) ? (en >> 3) : -1;
    }

    float c[4][4][4];
    #pragma unroll
    for (int i = 0; i < 4; i++)
        #pragma unroll
        for (int j = 0; j < 4; j++)
            #pragma unroll
            for (int q = 0; q < 4; q++) c[i][j][q] = 0.f;

    float4 ra[4];
    float  cv[16];
    auto ldA = [&](int k0) {
        int kk = (tid & 7) * 4;
        #pragma unroll
        for (int i = 0; i < 4; i++) {
            ra[i] = make_float4(0.f, 0.f, 0.f, 0.f);
            if (tok4[i] >= 0)
                ra[i] = *reinterpret_cast<const float4*>(curr + (size_t)tok4[i] * IN + k0 + kk);
        }
    };
    auto ldB = [&](int k0) {
        int n    = tid & 127;
        int kseg = (tid >> 7) * 16;
        const float* src = Bp + (size_t)(k0 + kseg) * PROJ + n;
        #pragma unroll
        for (int j = 0; j < 16; j++) cv[j] = src[(size_t)j * PROJ];
    };
    auto stAB = [&](int buf) {
        half* As = AsBase + buf * STG_H;
        half* Bs = BsBase + buf * STG_H;
        int kk = (tid & 7) * 4;
        #pragma unroll
        for (int i = 0; i < 4; i++) {
            int m = i * 32 + (tid >> 3);
            uint2 w;
            w.x = pk2(ra[i].x, ra[i].y);
            w.y = pk2(ra[i].z, ra[i].w);
            *reinterpret_cast<uint2*>(&As[m * TW + kk]) = w;
        }
        int n    = tid & 127;
        int kseg = (tid >> 7) * 16;
        #pragma unroll
        for (int j2 = 0; j2 < 4; j2++) {
            uint2 w;
            w.x = pk2(cv[j2*4+0], cv[j2*4+1]);
            w.y = pk2(cv[j2*4+2], cv[j2*4+3]);
            *reinterpret_cast<uint2*>(&Bs[n * TW + kseg + j2*4]) = w;
        }
    };
    auto domma = [&](int buf) {
        half* As = AsBase + buf * STG_H;
        half* Bs = BsBase + buf * STG_H;
        #pragma unroll
        for (int ks = 0; ks < 2; ks++) {
            int kb = ks * 16;
            unsigned a[4][4], b[4][2];
            #pragma unroll
            for (int mt = 0; mt < 4; mt++) {
                int r = wm0 + mt * 16 + lg;
                a[mt][0] = *reinterpret_cast<unsigned*>(&As[r * TW + kb + 2*lt]);
                a[mt][1] = *reinterpret_cast<unsigned*>(&As[(r + 8) * TW + kb + 2*lt]);
                a[mt][2] = *reinterpret_cast<unsigned*>(&As[r * TW + kb + 2*lt + 8]);
                a[mt][3] = *reinterpret_cast<unsigned*>(&As[(r + 8) * TW + kb + 2*lt + 8]);
            }
            #pragma unroll
            for (int nt = 0; nt < 4; nt++) {
                int cn = wn0 + nt * 8 + lg;
                b[nt][0] = *reinterpret_cast<unsigned*>(&Bs[cn * TW + kb + 2*lt]);
                b[nt][1] = *reinterpret_cast<unsigned*>(&Bs[cn * TW + kb + 2*lt + 8]);
            }
            #pragma unroll
            for (int mt = 0; mt < 4; mt++)
                #pragma unroll
                for (int nt = 0; nt < 4; nt++)
                    mmaf16(c[mt][nt], a[mt], b[nt]);
        }
    };

    ldA(0); ldB(0);
    stAB(0);
    __syncthreads();
    for (int ki = 0; ki < 32; ki++) {
        if (ki + 1 < 32) { ldA((ki + 1) * 32); ldB((ki + 1) * 32); }
        domma(ki & 1);
        if (ki + 1 < 32) { stAB((ki + 1) & 1); __syncthreads(); }
    }

    float alpha = sqrtf(scalep[0]);
    #pragma unroll
    for (int mt = 0; mt < 4; mt++) {
        #pragma unroll
        for (int ri = 0; ri < 2; ri++) {
            int rl = wm0 + mt * 16 + lg + ri * 8;
            int en = ent[rl];
            if (en < 0) continue;
            int token = en >> 3, h = en & 7;
            int b = token >> 10, s = token & 1023;
            unsigned* dst = g_qh + ((size_t)((b * NH + h) * SS + s)) * 64;
            #pragma unroll
            for (int nt = 0; nt < 4; nt++) {
                int cc = wn0 + nt * 8 + 2 * lt;
                dst[cc >> 1] = pk2(alpha * c[mt][nt][ri * 2 + 0],
                                   alpha * c[mt][nt][ri * 2 + 1]);
            }
        }
    }
}

// ---------------- oproj transpose+convert: [e][k][n] f32 -> [e][n][k] f16 ---
__global__ __launch_bounds__(256)
void oconv_kernel(const float* __restrict__ oproj)
{
    __shared__ float sm[32][33];
    int e  = blockIdx.z;
    int k0 = blockIdx.y * 32;
    int n0 = blockIdx.x * 32;
    int t  = threadIdx.x;
    int tr = t >> 5, tc = t & 31;

    const float* src = oproj + (size_t)e * PROJ * OUT;
    #pragma unroll
    for (int i = 0; i < 4; i++) {
        int k = k0 + tr + i * 8;
        sm[tr + i * 8][tc] = src[(size_t)k * OUT + n0 + tc];
    }
    __syncthreads();
    half* dst = g_oTh + (size_t)e * OUT * PROJ;
    #pragma unroll
    for (int i = 0; i < 4; i++) {
        int n = n0 + tr + i * 8;
        dst[(size_t)n * PROJ + k0 + tc] = __float2half_rn(sm[tc][tr + i * 8]);
    }
}

// ---------------- bucketed output projection (fp16 MMA, atomic add) ---------
#define FQW 136
__global__ __launch_bounds__(256, 2)
void obucket_kernel(float* __restrict__ out)
{
    extern __shared__ half hsm[];
    half* As = hsm;                       // 128 x 136
    half* Bs = hsm + 128*FQW;             // 128 x 136
    int*  ent = (int*)(hsm + 2*128*FQW);

    int e   = blockIdx.z;
    int cnt = g_cnt[e];
    int t0  = blockIdx.y * 128;
    if (t0 >= cnt) return;
    int n0  = blockIdx.x * 128;

    int tid = threadIdx.x;
    if (tid < 128)
        ent[tid] = (t0 + tid < cnt) ? g_list[e * BT + t0 + tid] : -1;
    __syncthreads();

    // A: g_r rows (already fp16)
    #pragma unroll
    for (int it = 0; it < 8; it++) {
        int lin = it * 256 + tid;
        int r = lin >> 4, c4 = lin & 15;
        int en = ent[r];
        uint4 v = make_uint4(0, 0, 0, 0);
        if (en >= 0)
            v = reinterpret_cast<const uint4*>(g_r)[(size_t)en * 16 + c4];
        *reinterpret_cast<uint4*>(&As[r * FQW + c4 * 8]) = v;
    }
    // B: pre-transposed fp16 oproj^T[e][n0+n][k] -> direct uint4 copies
    {
        const uint4* src = reinterpret_cast<const uint4*>(
            g_oTh + ((size_t)e * OUT + n0) * PROJ);
        #pragma unroll
        for (int it = 0; it < 8; it++) {
            int lin = it * 256 + tid;
            int r = lin >> 4, c4 = lin & 15;
            *reinterpret_cast<uint4*>(&Bs[r * FQW + c4 * 8]) = src[r * 16 + c4];
        }
    }
    __syncthreads();

    int wid = tid >> 5, lane = tid & 31;
    int wm0 = (wid & 1) * 64;
    int wn0 = (wid >> 1) * 32;
    int lg  = lane >> 2;
    int lt  = lane & 3;

    float c[4][4][4];
    #pragma unroll
    for (int i = 0; i < 4; i++)
        #pragma unroll
        for (int j = 0; j < 4; j++)
            #pragma unroll
            for (int q = 0; q < 4; q++) c[i][j][q] = 0.f;

    #pragma unroll
    for (int ks = 0; ks < 8; ks++) {
        int kb = ks * 16;
        unsigned a[4][4], b[4][2];
        #pragma unroll
        for (int mt = 0; mt < 4; mt++) {
            int r = wm0 + mt * 16 + lg;
            a[mt][0] = *reinterpret_cast<unsigned*>(&As[r * FQW + kb + 2*lt]);
            a[mt][1] = *reinterpret_cast<unsigned*>(&As[(r + 8) * FQW + kb + 2*lt]);
            a[mt][2] = *reinterpret_cast<unsigned*>(&As[r * FQW + kb + 2*lt + 8]);
            a[mt][3] = *reinterpret_cast<unsigned*>(&As[(r + 8) * FQW + kb + 2*lt + 8]);
        }
        #pragma unroll
        for (int nt = 0; nt < 4; nt++) {
            int cn = wn0 + nt * 8 + lg;
            b[nt][0] = *reinterpret_cast<unsigned*>(&Bs[cn * FQW + kb + 2*lt]);
            b[nt][1] = *reinterpret_cast<unsigned*>(&Bs[cn * FQW + kb + 2*lt + 8]);
        }
        #pragma unroll
        for (int mt = 0; mt < 4; mt++)
            #pragma unroll
            for (int nt = 0; nt < 4; nt++)
                mmaf16(c[mt][nt], a[mt], b[nt]);
    }

    #pragma unroll
    for (int mt = 0; mt < 4; mt++) {
        #pragma unroll
        for (int ri = 0; ri < 2; ri++) {
            int rl = wm0 + mt * 16 + lg + ri * 8;
            int en = ent[rl];
            if (en < 0) continue;
            int token = en >> 3;
            float* orow = out + (size_t)token * OUT;
            #pragma unroll
            for (int nt = 0; nt < 4; nt++) {
                int cc = n0 + wn0 + nt * 8 + 2 * lt;
                atomicAdd(&orow[cc],     c[mt][nt][ri * 2 + 0]);
                atomicAdd(&orow[cc + 1], c[mt][nt][ri * 2 + 1]);
            }
        }
    }
}

// ---------------- bucket build ----------------------------------------------
__global__ void qbucket_kernel()
{
    int i = blockIdx.x * 256 + threadIdx.x;
    if (i >= BT * NH) return;
    int e = g_selidx[i];
    int pos = atomicAdd(&g_cnt[e], 1);
    g_list[e * BT + pos] = i;
}

// ---------------- fused flash attention + relative-position band -------------
#define GW 198
__global__ __launch_bounds__(256)
void flash_kernel()
{
    extern __shared__ char smc[];
    half*     Qs   = (half*)smc;                        // 64 x 136
    half*     Ps   = Qs + 64*FQW;                       // 64 x 136
    half*     Kt   = Ps + 64*FQW;                       // 128 x 136
    half*     Kp   = Kt + 128*FQW;                      // 192 x 136 (kpos window)
    unsigned* Vt2  = (unsigned*)(Kp + 192*FQW);         // 64 x 136 (paired V)
    float*    Gs   = (float*)(Vt2 + 64*FQW);            // 64 x 198
    float*    redm = Gs + 64*GW;                        // 256
    float*    reds = redm + 256;                        // 256

    int zh = blockIdx.y;
    int b  = zh >> 3, h = zh & 7;
    int s0 = blockIdx.x * 64;
    int tid = threadIdx.x;
    int wid = tid >> 5, lane = tid & 31;
    int lg = lane >> 2, lt = lane & 3;
    int wm0 = (wid & 1) * 32;
    int wn0 = (wid >> 1) * 32;
    // G warp tiling: 16-row group + 9-tile half-window anchored at ws
    int gm = (wid & 3) * 16;
    int ws = 48 - gm;
    int ghalf = wid >> 2;
    int gc0 = ws + ghalf * 72;

    // Q tile 64x128 halves, direct fp16 copy
    {
        const uint4* qbase = reinterpret_cast<const uint4*>(g_qh + (size_t)(zh * SS + s0) * 64);
        #pragma unroll
        for (int it = 0; it < 4; it++) {
            int lin = it * 256 + tid;
            int r = lin >> 4, c4 = lin & 15;
            *reinterpret_cast<uint4*>(&Qs[r * FQW + c4 * 8]) = qbase[r * 16 + c4];
        }
    }

    float o[2][4][4];
    float mrow[2][2], lrow[2][2];
    #pragma unroll
    for (int mt = 0; mt < 2; mt++) {
        mrow[mt][0] = mrow[mt][1] = -1e30f;
        lrow[mt][0] = lrow[mt][1] = 0.f;
        #pragma unroll
        for (int nt = 0; nt < 4; nt++)
            #pragma unroll
            for (int q = 0; q < 4; q++) o[mt][nt][q] = 0.f;
    }

    for (int kt = 0; kt < 8; kt++) {
        int t0  = kt * 128;
        int bt0 = b * SS + t0;
        int base = t0 - s0 + 960;
        // K tile 128x128 halves, direct copy
        {
            const uint4* kbase = reinterpret_cast<const uint4*>(g_kh + (size_t)bt0 * 64);
            #pragma unroll
            for (int it = 0; it < 8; it++) {
                int lin = it * 256 + tid;
                int r = lin >> 4, c4 = lin & 15;
                *reinterpret_cast<uint4*>(&Kt[r * FQW + c4 * 8]) = kbase[r * 16 + c4];
            }
        }
        // V tile paired from fp16
        {
            const unsigned* vbase = g_vh + (size_t)bt0 * 64;
            #pragma unroll
            for (int it = 0; it < 8; it++) {
                int lin = it * 256 + tid;
                int tp = lin >> 5, p0 = (lin & 31) * 4;
                uint2 x = *reinterpret_cast<const uint2*>(vbase + (size_t)(2*tp) * 64 + (p0 >> 1));
                uint2 y = *reinterpret_cast<const uint2*>(vbase + (size_t)(2*tp + 1) * 64 + (p0 >> 1));
                uint4 w;
                w.x = __byte_perm(x.x, y.x, 0x5410);
                w.y = __byte_perm(x.x, y.x, 0x7632);
                w.z = __byte_perm(x.y, y.y, 0x5410);
                w.w = __byte_perm(x.y, y.y, 0x7632);
                *reinterpret_cast<uint4*>(&Vt2[tp * FQW + p0]) = w;
            }
        }
        // kpos window 192 rows (fp16, L2-resident)
        {
            const uint4* kp4 = reinterpret_cast<const uint4*>(g_kpos_h);
            #pragma unroll
            for (int it = 0; it < 12; it++) {
                int lin = it * 256 + tid;
                int w = lin >> 4, c4 = lin & 15;
                uint4 v = kp4[(size_t)(base + w) * 16 + c4];
                *reinterpret_cast<uint4*>(&Kp[w * FQW + c4 * 8]) = v;
            }
        }
        __syncthreads();

        // --- G = Q @ Kp^T, band-trimmed: 16 rows x 72 cols per warp ---
        {
            float gg[9][4];
            #pragma unroll
            for (int nt = 0; nt < 9; nt++)
                #pragma unroll
                for (int q = 0; q < 4; q++) gg[nt][q] = 0.f;
            #pragma unroll
            for (int ks = 0; ks < 8; ks++) {
                int kb = ks * 16;
                unsigned a[4], bf[9][2];
                a[0] = *reinterpret_cast<unsigned*>(&Qs[(gm + lg) * FQW + kb + 2*lt]);
                a[1] = *reinterpret_cast<unsigned*>(&Qs[(gm + 8 + lg) * FQW + kb + 2*lt]);
                a[2] = *reinterpret_cast<unsigned*>(&Qs[(gm + lg) * FQW + kb + 2*lt + 8]);
                a[3] = *reinterpret_cast<unsigned*>(&Qs[(gm + 8 + lg) * FQW + kb + 2*lt + 8]);
                #pragma unroll
                for (int nt = 0; nt < 9; nt++) {
                    int cn = gc0 + nt * 8 + lg;
                    bf[nt][0] = *reinterpret_cast<unsigned*>(&Kp[cn * FQW + kb + 2*lt]);
                    bf[nt][1] = *reinterpret_cast<unsigned*>(&Kp[cn * FQW + kb + 2*lt + 8]);
                }
                #pragma unroll
                for (int nt = 0; nt < 9; nt++)
                    mmaf16(gg[nt], a, bf[nt]);
            }
            #pragma unroll
            for (int nt = 0; nt < 9; nt++) {
                int col = gc0 + nt * 8 + 2 * lt;
                *reinterpret_cast<float2*>(&Gs[(gm + lg) * GW + col]) =
                    make_float2(gg[nt][0], gg[nt][1]);
                *reinterpret_cast<float2*>(&Gs[(gm + 8 + lg) * GW + col]) =
                    make_float2(gg[nt][2], gg[nt][3]);
            }
        }

        // --- S = Q K^T ---
        float s_[2][4][4];
        #pragma unroll
        for (int mt = 0; mt < 2; mt++)
            #pragma unroll
            for (int nt = 0; nt < 4; nt++)
                #pragma unroll
                for (int q = 0; q < 4; q++) s_[mt][nt][q] = 0.f;
        #pragma unroll
        for (int ks = 0; ks < 8; ks++) {
            int kb = ks * 16;
            unsigned a[2][4], bf[4][2];
            #pragma unroll
            for (int mt = 0; mt < 2; mt++) {
                int r = wm0 + mt * 16 + lg;
                a[mt][0] = *reinterpret_cast<unsigned*>(&Qs[r * FQW + kb + 2*lt]);
                a[mt][1] = *reinterpret_cast<unsigned*>(&Qs[(r + 8) * FQW + kb + 2*lt]);
                a[mt][2] = *reinterpret_cast<unsigned*>(&Qs[r * FQW + kb + 2*lt + 8]);
                a[mt][3] = *reinterpret_cast<unsigned*>(&Qs[(r + 8) * FQW + kb + 2*lt + 8]);
            }
            #pragma unroll
            for (int nt = 0; nt < 4; nt++) {
                int cn = wn0 + nt * 8 + lg;
                bf[nt][0] = *reinterpret_cast<unsigned*>(&Kt[cn * FQW + kb + 2*lt]);
                bf[nt][1] = *reinterpret_cast<unsigned*>(&Kt[cn * FQW + kb + 2*lt + 8]);
            }
            #pragma unroll
            for (int mt = 0; mt < 2; mt++)
                #pragma unroll
                for (int nt = 0; nt < 4; nt++)
                    mmaf16(s_[mt][nt], a[mt], bf[nt]);
        }
        __syncthreads();   // Gs complete

        // band add: S[i,j] += G[i, j-i+63]
        #pragma unroll
        for (int mt = 0; mt < 2; mt++) {
            #pragma unroll
            for (int ri = 0; ri < 2; ri++) {
                int i = wm0 + mt * 16 + lg + ri * 8;
                const float* grow = Gs + (size_t)i * GW - i + 63;
                #pragma unroll
                for (int nt = 0; nt < 4; nt++) {
                    int j = wn0 + nt * 8 + 2 * lt;
                    s_[mt][nt][ri * 2 + 0] += grow[j];
                    s_[mt][nt][ri * 2 + 1] += grow[j + 1];
                }
            }
        }

        // row max
        #pragma unroll
        for (int mt = 0; mt < 2; mt++) {
            #pragma unroll
            for (int ri = 0; ri < 2; ri++) {
                float v = -1e30f;
                #pragma unroll
                for (int nt = 0; nt < 4; nt++)
                    v = fmaxf(v, fmaxf(s_[mt][nt][ri * 2], s_[mt][nt][ri * 2 + 1]));
                v = fmaxf(v, __shfl_xor_sync(0xffffffff, v, 1));
                v = fmaxf(v, __shfl_xor_sync(0xffffffff, v, 2));
                if (lt == 0) {
                    int rl = wm0 + mt * 16 + lg + ri * 8;
                    redm[rl * 4 + (wid >> 1)] = v;
                }
            }
        }
        __syncthreads();

        float scl[2][2];
        #pragma unroll
        for (int mt = 0; mt < 2; mt++) {
            #pragma unroll
            for (int ri = 0; ri < 2; ri++) {
                int rl = wm0 + mt * 16 + lg + ri * 8;
                float v = fmaxf(fmaxf(redm[rl * 4 + 0], redm[rl * 4 + 1]),
                                fmaxf(redm[rl * 4 + 2], redm[rl * 4 + 3]));
                float mnew = fmaxf(mrow[mt][ri], v);
                scl[mt][ri] = __expf(mrow[mt][ri] - mnew);
                mrow[mt][ri] = mnew;
            }
        }

        #pragma unroll
        for (int mt = 0; mt < 2; mt++) {
            #pragma unroll
            for (int ri = 0; ri < 2; ri++) {
                float m = mrow[mt][ri];
                float sum = 0.f;
                int r = wm0 + mt * 16 + lg + ri * 8;
                #pragma unroll
                for (int nt = 0; nt < 4; nt++) {
                    float e0 = __expf(s_[mt][nt][ri * 2 + 0] - m);
                    float e1 = __expf(s_[mt][nt][ri * 2 + 1] - m);
                    sum += e0 + e1;
                    int c0 = wn0 + nt * 8 + 2 * lt;
                    *reinterpret_cast<unsigned*>(&Ps[r * FQW + c0]) = pk2(e0, e1);
                    o[mt][nt][ri * 2 + 0] *= scl[mt][ri];
                    o[mt][nt][ri * 2 + 1] *= scl[mt][ri];
                }
                sum += __shfl_xor_sync(0xffffffff, sum, 1);
                sum += __shfl_xor_sync(0xffffffff, sum, 2);
                if (lt == 0) reds[r * 4 + (wid >> 1)] = sum;
            }
        }
        __syncthreads();

        #pragma unroll
        for (int mt = 0; mt < 2; mt++) {
            #pragma unroll
            for (int ri = 0; ri < 2; ri++) {
                int rl = wm0 + mt * 16 + lg + ri * 8;
                float ltile = reds[rl * 4 + 0] + reds[rl * 4 + 1]
                            + reds[rl * 4 + 2] + reds[rl * 4 + 3];
                lrow[mt][ri] = lrow[mt][ri] * scl[mt][ri] + ltile;
            }
        }

        // O += P @ V
        #pragma unroll
        for (int ks = 0; ks < 8; ks++) {
            int kb = ks * 16;
            unsigned a[2][4], bf[4][2];
            #pragma unroll
            for (int mt = 0; mt < 2; mt++) {
                int r = wm0 + mt * 16 + lg;
                a[mt][0] = *reinterpret_cast<unsigned*>(&Ps[r * FQW + kb + 2*lt]);
                a[mt][1] = *reinterpret_cast<unsigned*>(&Ps[(r + 8) * FQW + kb + 2*lt]);
                a[mt][2] = *reinterpret_cast<unsigned*>(&Ps[r * FQW + kb + 2*lt + 8]);
                a[mt][3] = *reinterpret_cast<unsigned*>(&Ps[(r + 8) * FQW + kb + 2*lt + 8]);
            }
            #pragma unroll
            for (int nt = 0; nt < 4; nt++) {
                int col = wn0 + nt * 8 + lg;
                bf[nt][0] = Vt2[(kb/2 + lt) * FQW + col];
                bf[nt][1] = Vt2[(kb/2 + lt + 4) * FQW + col];
            }
            #pragma unroll
            for (int mt = 0; mt < 2; mt++)
                #pragma unroll
                for (int nt = 0; nt < 4; nt++)
                    mmaf16(o[mt][nt], a[mt], bf[nt]);
        }
        __syncthreads();
    }

    // epilogue: normalize, gate, write fp16 rows to g_r[(token*NH+h)]
    #pragma unroll
    for (int mt = 0; mt < 2; mt++) {
        #pragma unroll
        for (int ri = 0; ri < 2; ri++) {
            int sglob = s0 + wm0 + mt * 16 + lg + ri * 8;
            int token = b * SS + sglob;
            float g = g_selval[token * NH + h];
            float inv = g / lrow[mt][ri];
            unsigned* rrow = g_r + ((size_t)token * NH + h) * 64;
            #pragma unroll
            for (int nt = 0; nt < 4; nt++) {
                int c0 = wn0 + nt * 8 + 2 * lt;
                rrow[c0 >> 1] = pk2(o[mt][nt][ri * 2 + 0] * inv,
                                    o[mt][nt][ri * 2 + 1] * inv);
            }
        }
    }
}

// ---------------- sel = curr @ sel_dst^T, top-8, sigmoid --------------------
__global__ void sel_topk_kernel(const float* __restrict__ curr,
                                const float* __restrict__ sdst)
{
    __shared__ float srow[IN];
    __shared__ float wsum[NE][4];
    __shared__ float vals[NE];
    int bs = blockIdx.x;
    int tid = threadIdx.x;
    const float* row = curr + (long)bs * IN;
    for (int i = tid; i < IN; i += 128) srow[i] = row[i];
    __syncthreads();

    float acc[NE];
    #pragma unroll
    for (int e = 0; e < NE; e++) acc[e] = 0.f;
    for (int i = tid; i < IN; i += 128) {
        float c = srow[i];
        #pragma unroll
        for (int e = 0; e < NE; e++)
            acc[e] = fmaf(c, sdst[e*IN + i], acc[e]);
    }
    int lane = tid & 31, w = tid >> 5;
    #pragma unroll
    for (int e = 0; e < NE; e++) {
        float v = acc[e];
        #pragma unroll
        for (int o = 16; o > 0; o >>= 1) v += __shfl_xor_sync(0xffffffff, v, o);
        if (lane == 0) wsum[e][w] = v;
    }
    __syncthreads();
    if (tid < NE) vals[tid] = wsum[tid][0] + wsum[tid][1] + wsum[tid][2] + wsum[tid][3];
    __syncthreads();
    if (tid == 0) {
        bool used[NE];
        #pragma unroll
        for (int e = 0; e < NE; e++) used[e] = false;
        for (int h = 0; h < NH; h++) {
            int bi = 0; float bv = -3.4e38f;
            for (int e = 0; e < NE; e++)
                if (!used[e] && vals[e] > bv) { bv = vals[e]; bi = e; }
            used[bi] = true;
            g_selidx[bs*NH + h] = bi;
            g_selval[bs*NH + h] = 1.f / (1.f + expf(-bv));
        }
    }
}

// ---------------- sinusoidal embedding --------------------------------------
__global__ void pemb_kernel()
{
    int i = blockIdx.x;
    int tid = threadIdx.x;
    float pos = (float)i - (float)(SS - 1);
    float cst = -logf(10000.f) / (float)IN;
    for (int j = tid; j < IN/2; j += 256) {
        float dv = expf((float)(2*j) * cst);
        float s, co;
        sincosf(pos * dv, &s, &co);
        g_pemb[(long)i*IN + 2*j]     = s;
        g_pemb[(long)i*IN + 2*j + 1] = co;
    }
}

// ---------------- launch ----------------------------------------------------
static char* symc(const void* sym) { void* p = nullptr; cudaGetSymbolAddress(&p, sym); return (char*)p; }

extern "C" void kernel_launch(void* const* d_in, const int* in_sizes, int n_in,
                              void* d_out, int out_size)
{
    const float* curr  = (const float*)d_in[0];
    const float* attn  = (const float*)d_in[1];
    const float* dtq   = (const float*)d_in[2];
    const float* dtkv  = (const float*)d_in[3];
    const float* oproj = (const float*)d_in[4];
    const float* ptpk  = (const float*)d_in[5];
    const float* sdst  = (const float*)d_in[6];
    const float* scale = (const float*)d_in[7];
    float* out = (float*)d_out;

    float* p_pemb   = (float*)symc(g_pemb);
    char*  p_cnt    = symc(g_cnt);
    char*  p_kpos_h = symc(g_kpos_h);

    static int init_done = 0;
    static cudaStream_t s1, s2;
    static cudaEvent_t evRoot, ev1, ev2;
    const int FLASH_SMEM = (64*FQW + 64*FQW + 128*FQW + 192*FQW)*2
                         + 64*FQW*4
                         + 64*GW*4 + 512*4;
    const int OB_SMEM = 2*128*FQW*2 + 128*4;
    if (!init_done) {
        cudaFuncSetAttribute(flash_kernel,
            cudaFuncAttributeMaxDynamicSharedMemorySize, FLASH_SMEM);
        cudaFuncSetAttribute(tgemm<0>,
            cudaFuncAttributeMaxDynamicSharedMemorySize, TG_SMEM);
        cudaFuncSetAttribute(tgemm<1>,
            cudaFuncAttributeMaxDynamicSharedMemorySize, TG_SMEM);
        cudaFuncSetAttribute(qexp_kernel,
            cudaFuncAttributeMaxDynamicSharedMemorySize, QX_SMEM);
        cudaFuncSetAttribute(obucket_kernel,
            cudaFuncAttributeMaxDynamicSharedMemorySize, OB_SMEM);
        cudaStreamCreateWithFlags(&s1, cudaStreamNonBlocking);
        cudaStreamCreateWithFlags(&s2, cudaStreamNonBlocking);
        cudaEventCreateWithFlags(&evRoot, cudaEventDisableTiming);
        cudaEventCreateWithFlags(&ev1, cudaEventDisableTiming);
        cudaEventCreateWithFlags(&ev2, cudaEventDisableTiming);
        init_done = 1;
    }

    // fork
    cudaEventRecord(evRoot, 0);
    cudaStreamWaitEvent(s1, evRoot, 0);
    cudaStreamWaitEvent(s2, evRoot, 0);

    // s1: expert selection + buckets + q projection
    cudaMemsetAsync(p_cnt, 0, NE * sizeof(int), s1);
    sel_topk_kernel<<<BT, 128, 0, s1>>>(curr, sdst);
    qbucket_kernel<<<(BT*NH + 255)/256, 256, 0, s1>>>();
    qexp_kernel<<<dim3(1, 32, NE), 256, QX_SMEM, s1>>>(curr, dtq, scale);
    cudaEventRecord(ev1, s1);

    // s2: positional embedding + kpos + kv
    pemb_kernel<<<RLEN, 256, 0, s2>>>();
    cudaMemsetAsync(p_kpos_h + (size_t)RLEN * 64 * 4, 0, 64 * 4, s2);
    tgemm<1><<<dim3(1, 16, 1), 256, TG_SMEM, s2>>>(p_pemb, ptpk, nullptr,
        RLEN, PROJ, IN, IN, IN, PROJ, scale, 3);
    tgemm<0><<<dim3(2, 32, 1), 256, TG_SMEM, s2>>>(attn, dtkv, nullptr,
        BT, 2*PROJ, IN, IN, 2*PROJ, 2*PROJ, scale, 2);
    cudaEventRecord(ev2, s2);

    // default: zero out + transpose oproj while producers run, then join
    cudaMemsetAsync(out, 0, (size_t)BT * OUT * sizeof(float));
    oconv_kernel<<<dim3(OUT/32, PROJ/32, NE), 256>>>(oproj);
    cudaStreamWaitEvent(0, ev1, 0);
    cudaStreamWaitEvent(0, ev2, 0);

    // fused attention
    flash_kernel<<<dim3(16, BB*NH), 256, FLASH_SMEM>>>();

    // bucketed output projection (atomic accumulate over heads)
    obucket_kernel<<<dim3(8, 32, NE), 256, OB_SMEM>>>(out);
}

// round 16
// speedup vs baseline: 1.0684x; 1.0178x over previous
#include <cuda_runtime.h>
#include <cuda_fp16.h>
#include <math.h>

#define BB 4
#define SS 1024
#define IN 1024
#define OUT 1024
#define NH 8
#define NE 16
#define PROJ 128
#define BT (BB*SS)
#define RLEN (2*SS-1)

// ---------------- scratch ----------------------------------------------------
__device__ float    g_selval[BT*NH];
__device__ int      g_selidx[BT*NH];
__device__ int      g_cnt[NE];
__device__ int      g_list[NE*BT];
__device__ unsigned g_kh  [(size_t)BT*64];             // K * sc, fp16x2
__device__ unsigned g_vh  [(size_t)BT*64];             // V, fp16x2
__device__ float    g_pemb[(size_t)RLEN*IN];
__device__ unsigned g_kpos_h[(size_t)(RLEN+1)*64];     // kpos * sc, fp16x2 (+pad row)
__device__ unsigned g_qh  [(size_t)BB*NH*SS*64];       // Q * sc, fp16x2
__device__ unsigned g_r   [(size_t)BT*NH*64];          // gated attn out, fp16x2
__device__ half     g_oTh [(size_t)NE*OUT*PROJ];       // oproj^T fp16 [e][n][k]

// ---------------- fp16 helpers ----------------------------------------------
__device__ __forceinline__ unsigned pk2(float x, float y) {
    __half2 h = __floats2half2_rn(x, y);
    return *reinterpret_cast<unsigned*>(&h);
}
__device__ __forceinline__ void mmaf16(float c[4], const unsigned a[4],
                                       const unsigned b[2]) {
    asm volatile(
        "mma.sync.aligned.m16n8k16.row.col.f32.f16.f16.f32 "
        "{%0,%1,%2,%3},{%4,%5,%6,%7},{%8,%9},{%0,%1,%2,%3};"
        : "+f"(c[0]), "+f"(c[1]), "+f"(c[2]), "+f"(c[3])
        : "r"(a[0]), "r"(a[1]), "r"(a[2]), "r"(a[3]),
          "r"(b[0]), "r"(b[1]));
}
__device__ __forceinline__ void red2(float* addr, float v0, float v1) {
    asm volatile("red.global.add.v2.f32 [%0], {%1, %2};"
                 :: "l"(addr), "f"(v0), "f"(v1) : "memory");
}

// tile geometry for generic GEMM
#define TW 40
#define STG_H (128*TW)
#define TG_SMEM (4*STG_H*2)
#define QX_SMEM (TG_SMEM + 128*4)

// ---------------- fp16 tensor GEMM, double-buffered ------------------------
// TRANSB=0: B row-major KxN. TRANSB=1: B row-major NxK (A @ B^T).
// alphaMode: 0 plain fp32 C, 2 split-kv fp16 epilogue (k*sc | v),
//            3 kpos fp16 epilogue (*sqrt(scale) -> g_kpos_h)
template<int TRANSB>
__global__ __launch_bounds__(256, 2)
void tgemm(const float* __restrict__ A, const float* __restrict__ Bm,
           float* __restrict__ C,
           int M, int N, int K, int lda, int ldb, int ldc,
           const float* __restrict__ scalep, int alphaMode)
{
    extern __shared__ half hsm[];
    half* AsBase = hsm;
    half* BsBase = hsm + 2*STG_H;

    const float* Ap = A;
    const float* Bp = Bm;
    float*       Cp = C;
    int m0 = blockIdx.y * 128;
    int n0 = blockIdx.x * 128;

    int tid  = threadIdx.x;
    int wid  = tid >> 5, lane = tid & 31;
    int wm0  = (wid & 1) * 64;
    int wn0  = (wid >> 1) * 32;
    int lg   = lane >> 2;
    int lt   = lane & 3;

    float c[4][4][4];
    #pragma unroll
    for (int i = 0; i < 4; i++)
        #pragma unroll
        for (int j = 0; j < 4; j++)
            #pragma unroll
            for (int q = 0; q < 4; q++) c[i][j][q] = 0.f;

    float4 ra[4];
    float4 rb4[4];
    float  cv[16];

    auto ldA = [&](int k0) {
        #pragma unroll
        for (int i = 0; i < 4; i++) {
            int m  = i * 32 + (tid >> 3);
            int kk = (tid & 7) * 4;
            ra[i] = make_float4(0.f, 0.f, 0.f, 0.f);
            if (m0 + m < M)
                ra[i] = *reinterpret_cast<const float4*>(Ap + (long)(m0 + m) * lda + k0 + kk);
        }
    };
    auto ldB = [&](int k0) {
        if (TRANSB == 0) {
            int n    = tid & 127;
            int kseg = (tid >> 7) * 16;
            const float* src = Bp + (long)(k0 + kseg) * ldb + n0 + n;
            #pragma unroll
            for (int j = 0; j < 16; j++) cv[j] = src[(long)j * ldb];
        } else {
            #pragma unroll
            for (int i = 0; i < 4; i++) {
                int nn = i * 32 + (tid >> 3);
                int kk = (tid & 7) * 4;
                rb4[i] = make_float4(0.f, 0.f, 0.f, 0.f);
                if (n0 + nn < N)
                    rb4[i] = *reinterpret_cast<const float4*>(Bp + (long)(n0 + nn) * ldb + k0 + kk);
            }
        }
    };
    auto stAB = [&](int buf) {
        half* As = AsBase + buf * STG_H;
        half* Bs = BsBase + buf * STG_H;
        #pragma unroll
        for (int i = 0; i < 4; i++) {
            int m  = i * 32 + (tid >> 3);
            int kk = (tid & 7) * 4;
            uint2 w;
            w.x = pk2(ra[i].x, ra[i].y);
            w.y = pk2(ra[i].z, ra[i].w);
            *reinterpret_cast<uint2*>(&As[m * TW + kk]) = w;
        }
        if (TRANSB == 0) {
            int n    = tid & 127;
            int kseg = (tid >> 7) * 16;
            #pragma unroll
            for (int j2 = 0; j2 < 4; j2++) {
                uint2 w;
                w.x = pk2(cv[j2*4+0], cv[j2*4+1]);
                w.y = pk2(cv[j2*4+2], cv[j2*4+3]);
                *reinterpret_cast<uint2*>(&Bs[n * TW + kseg + j2*4]) = w;
            }
        } else {
            #pragma unroll
            for (int i = 0; i < 4; i++) {
                int nn = i * 32 + (tid >> 3);
                int kk = (tid & 7) * 4;
                uint2 w;
                w.x = pk2(rb4[i].x, rb4[i].y);
                w.y = pk2(rb4[i].z, rb4[i].w);
                *reinterpret_cast<uint2*>(&Bs[nn * TW + kk]) = w;
            }
        }
    };
    auto domma = [&](int buf) {
        half* As = AsBase + buf * STG_H;
        half* Bs = BsBase + buf * STG_H;
        #pragma unroll
        for (int ks = 0; ks < 2; ks++) {
            int kb = ks * 16;
            unsigned a[4][4], b[4][2];
            #pragma unroll
            for (int mt = 0; mt < 4; mt++) {
                int r = wm0 + mt * 16 + lg;
                a[mt][0] = *reinterpret_cast<unsigned*>(&As[r * TW + kb + 2*lt]);
                a[mt][1] = *reinterpret_cast<unsigned*>(&As[(r + 8) * TW + kb + 2*lt]);
                a[mt][2] = *reinterpret_cast<unsigned*>(&As[r * TW + kb + 2*lt + 8]);
                a[mt][3] = *reinterpret_cast<unsigned*>(&As[(r + 8) * TW + kb + 2*lt + 8]);
            }
            #pragma unroll
            for (int nt = 0; nt < 4; nt++) {
                int cn = wn0 + nt * 8 + lg;
                b[nt][0] = *reinterpret_cast<unsigned*>(&Bs[cn * TW + kb + 2*lt]);
                b[nt][1] = *reinterpret_cast<unsigned*>(&Bs[cn * TW + kb + 2*lt + 8]);
            }
            #pragma unroll
            for (int mt = 0; mt < 4; mt++)
                #pragma unroll
                for (int nt = 0; nt < 4; nt++)
                    mmaf16(c[mt][nt], a[mt], b[nt]);
        }
    };

    int nk = K / 32;
    ldA(0); ldB(0);
    stAB(0);
    __syncthreads();
    for (int ki = 0; ki < nk; ki++) {
        if (ki + 1 < nk) { ldA((ki + 1) * 32); ldB((ki + 1) * 32); }
        domma(ki & 1);
        if (ki + 1 < nk) {
            stAB((ki + 1) & 1);
            __syncthreads();
        }
    }

    if (alphaMode == 2) {
        float sc = sqrtf(scalep[0]);
        #pragma unroll
        for (int mt = 0; mt < 4; mt++) {
            #pragma unroll
            for (int nt = 0; nt < 4; nt++) {
                #pragma unroll
                for (int ri = 0; ri < 2; ri++) {
                    int r  = m0 + wm0 + mt * 16 + lg + ri * 8;
                    int cc = n0 + wn0 + nt * 8 + 2 * lt;
                    float v0 = c[mt][nt][ri * 2 + 0];
                    float v1 = c[mt][nt][ri * 2 + 1];
                    if (cc < PROJ)
                        g_kh[(size_t)r * 64 + (cc >> 1)] = pk2(sc * v0, sc * v1);
                    else
                        g_vh[(size_t)r * 64 + ((cc - PROJ) >> 1)] = pk2(v0, v1);
                }
            }
        }
        return;
    }
    if (alphaMode == 3) {
        float sc = sqrtf(scalep[0]);
        #pragma unroll
        for (int mt = 0; mt < 4; mt++) {
            #pragma unroll
            for (int ri = 0; ri < 2; ri++) {
                int r = m0 + wm0 + mt * 16 + lg + ri * 8;
                if (r >= M) continue;
                #pragma unroll
                for (int nt = 0; nt < 4; nt++) {
                    int cc = n0 + wn0 + nt * 8 + 2 * lt;
                    g_kpos_h[(size_t)r * 64 + (cc >> 1)] =
                        pk2(sc * c[mt][nt][ri * 2 + 0], sc * c[mt][nt][ri * 2 + 1]);
                }
            }
        }
        return;
    }

    #pragma unroll
    for (int mt = 0; mt < 4; mt++) {
        #pragma unroll
        for (int nt = 0; nt < 4; nt++) {
            int r  = m0 + wm0 + mt * 16 + lg;
            int cc = n0 + wn0 + nt * 8 + 2 * lt;
            if (r < M) {
                if (cc     < N) Cp[(long)r * ldc + cc]     = c[mt][nt][0];
                if (cc + 1 < N) Cp[(long)r * ldc + cc + 1] = c[mt][nt][1];
            }
            if (r + 8 < M) {
                if (cc     < N) Cp[(long)(r + 8) * ldc + cc]     = c[mt][nt][2];
                if (cc + 1 < N) Cp[(long)(r + 8) * ldc + cc + 1] = c[mt][nt][3];
            }
        }
    }
}

// ---------------- expert-bucketed q projection (fp16 MMA, fp16 out) ---------
__global__ __launch_bounds__(256, 2)
void qexp_kernel(const float* __restrict__ curr, const float* __restrict__ dtq,
                 const float* __restrict__ scalep)
{
    extern __shared__ half hsm[];
    half* AsBase = hsm;
    half* BsBase = hsm + 2*STG_H;
    int*  ent    = (int*)(hsm + 4*STG_H);

    int e   = blockIdx.z;
    int cnt = g_cnt[e];
    int t0  = blockIdx.y * 128;
    if (t0 >= cnt) return;

    int tid  = threadIdx.x;
    if (tid < 128)
        ent[tid] = (t0 + tid < cnt) ? g_list[e * BT + t0 + tid] : -1;
    __syncthreads();

    const float* Bp = dtq + (size_t)e * IN * PROJ;

    int wid  = tid >> 5, lane = tid & 31;
    int wm0  = (wid & 1) * 64;
    int wn0  = (wid >> 1) * 32;
    int lg   = lane >> 2;
    int lt   = lane & 3;

    int tok4[4];
    #pragma unroll
    for (int i = 0; i < 4; i++) {
        int m = i * 32 + (tid >> 3);
        int en = ent[m];
        tok4[i] = (en >= 0) ? (en >> 3) : -1;
    }

    float c[4][4][4];
    #pragma unroll
    for (int i = 0; i < 4; i++)
        #pragma unroll
        for (int j = 0; j < 4; j++)
            #pragma unroll
            for (int q = 0; q < 4; q++) c[i][j][q] = 0.f;

    float4 ra[4];
    float  cv[16];
    auto ldA = [&](int k0) {
        int kk = (tid & 7) * 4;
        #pragma unroll
        for (int i = 0; i < 4; i++) {
            ra[i] = make_float4(0.f, 0.f, 0.f, 0.f);
            if (tok4[i] >= 0)
                ra[i] = *reinterpret_cast<const float4*>(curr + (size_t)tok4[i] * IN + k0 + kk);
        }
    };
    auto ldB = [&](int k0) {
        int n    = tid & 127;
        int kseg = (tid >> 7) * 16;
        const float* src = Bp + (size_t)(k0 + kseg) * PROJ + n;
        #pragma unroll
        for (int j = 0; j < 16; j++) cv[j] = src[(size_t)j * PROJ];
    };
    auto stAB = [&](int buf) {
        half* As = AsBase + buf * STG_H;
        half* Bs = BsBase + buf * STG_H;
        int kk = (tid & 7) * 4;
        #pragma unroll
        for (int i = 0; i < 4; i++) {
            int m = i * 32 + (tid >> 3);
            uint2 w;
            w.x = pk2(ra[i].x, ra[i].y);
            w.y = pk2(ra[i].z, ra[i].w);
            *reinterpret_cast<uint2*>(&As[m * TW + kk]) = w;
        }
        int n    = tid & 127;
        int kseg = (tid >> 7) * 16;
        #pragma unroll
        for (int j2 = 0; j2 < 4; j2++) {
            uint2 w;
            w.x = pk2(cv[j2*4+0], cv[j2*4+1]);
            w.y = pk2(cv[j2*4+2], cv[j2*4+3]);
            *reinterpret_cast<uint2*>(&Bs[n * TW + kseg + j2*4]) = w;
        }
    };
    auto domma = [&](int buf) {
        half* As = AsBase + buf * STG_H;
        half* Bs = BsBase + buf * STG_H;
        #pragma unroll
        for (int ks = 0; ks < 2; ks++) {
            int kb = ks * 16;
            unsigned a[4][4], b[4][2];
            #pragma unroll
            for (int mt = 0; mt < 4; mt++) {
                int r = wm0 + mt * 16 + lg;
                a[mt][0] = *reinterpret_cast<unsigned*>(&As[r * TW + kb + 2*lt]);
                a[mt][1] = *reinterpret_cast<unsigned*>(&As[(r + 8) * TW + kb + 2*lt]);
                a[mt][2] = *reinterpret_cast<unsigned*>(&As[r * TW + kb + 2*lt + 8]);
                a[mt][3] = *reinterpret_cast<unsigned*>(&As[(r + 8) * TW + kb + 2*lt + 8]);
            }
            #pragma unroll
            for (int nt = 0; nt < 4; nt++) {
                int cn = wn0 + nt * 8 + lg;
                b[nt][0] = *reinterpret_cast<unsigned*>(&Bs[cn * TW + kb + 2*lt]);
                b[nt][1] = *reinterpret_cast<unsigned*>(&Bs[cn * TW + kb + 2*lt + 8]);
            }
            #pragma unroll
            for (int mt = 0; mt < 4; mt++)
                #pragma unroll
                for (int nt = 0; nt < 4; nt++)
                    mmaf16(c[mt][nt], a[mt], b[nt]);
        }
    };

    ldA(0); ldB(0);
    stAB(0);
    __syncthreads();
    for (int ki = 0; ki < 32; ki++) {
        if (ki + 1 < 32) { ldA((ki + 1) * 32); ldB((ki + 1) * 32); }
        domma(ki & 1);
        if (ki + 1 < 32) { stAB((ki + 1) & 1); __syncthreads(); }
    }

    float alpha = sqrtf(scalep[0]);
    #pragma unroll
    for (int mt = 0; mt < 4; mt++) {
        #pragma unroll
        for (int ri = 0; ri < 2; ri++) {
            int rl = wm0 + mt * 16 + lg + ri * 8;
            int en = ent[rl];
            if (en < 0) continue;
            int token = en >> 3, h = en & 7;
            int b = token >> 10, s = token & 1023;
            unsigned* dst = g_qh + ((size_t)((b * NH + h) * SS + s)) * 64;
            #pragma unroll
            for (int nt = 0; nt < 4; nt++) {
                int cc = wn0 + nt * 8 + 2 * lt;
                dst[cc >> 1] = pk2(alpha * c[mt][nt][ri * 2 + 0],
                                   alpha * c[mt][nt][ri * 2 + 1]);
            }
        }
    }
}

// ---------------- oproj transpose+convert: [e][k][n] f32 -> [e][n][k] f16 ---
__global__ __launch_bounds__(256)
void oconv_kernel(const float* __restrict__ oproj)
{
    __shared__ float sm[32][33];
    int e  = blockIdx.z;
    int k0 = blockIdx.y * 32;
    int n0 = blockIdx.x * 32;
    int t  = threadIdx.x;
    int tr = t >> 5, tc = t & 31;

    const float* src = oproj + (size_t)e * PROJ * OUT;
    #pragma unroll
    for (int i = 0; i < 4; i++) {
        int k = k0 + tr + i * 8;
        sm[tr + i * 8][tc] = src[(size_t)k * OUT + n0 + tc];
    }
    __syncthreads();
    half* dst = g_oTh + (size_t)e * OUT * PROJ;
    #pragma unroll
    for (int i = 0; i < 4; i++) {
        int n = n0 + tr + i * 8;
        dst[(size_t)n * PROJ + k0 + tc] = __float2half_rn(sm[tc][tr + i * 8]);
    }
}

// ---------------- bucketed output projection (fp16 MMA, red.v2 add) ---------
#define FQW 136
__global__ __launch_bounds__(256, 2)
void obucket_kernel(float* __restrict__ out)
{
    extern __shared__ half hsm[];
    half* As = hsm;                       // 128 x 136
    half* Bs = hsm + 128*FQW;             // 128 x 136
    int*  ent = (int*)(hsm + 2*128*FQW);

    int e   = blockIdx.z;
    int cnt = g_cnt[e];
    int t0  = blockIdx.y * 128;
    if (t0 >= cnt) return;
    int n0  = blockIdx.x * 128;

    int tid = threadIdx.x;
    if (tid < 128)
        ent[tid] = (t0 + tid < cnt) ? g_list[e * BT + t0 + tid] : -1;
    __syncthreads();

    // A: g_r rows (already fp16)
    #pragma unroll
    for (int it = 0; it < 8; it++) {
        int lin = it * 256 + tid;
        int r = lin >> 4, c4 = lin & 15;
        int en = ent[r];
        uint4 v = make_uint4(0, 0, 0, 0);
        if (en >= 0)
            v = reinterpret_cast<const uint4*>(g_r)[(size_t)en * 16 + c4];
        *reinterpret_cast<uint4*>(&As[r * FQW + c4 * 8]) = v;
    }
    // B: pre-transposed fp16 oproj^T[e][n0+n][k] -> direct uint4 copies
    {
        const uint4* src = reinterpret_cast<const uint4*>(
            g_oTh + ((size_t)e * OUT + n0) * PROJ);
        #pragma unroll
        for (int it = 0; it < 8; it++) {
            int lin = it * 256 + tid;
            int r = lin >> 4, c4 = lin & 15;
            *reinterpret_cast<uint4*>(&Bs[r * FQW + c4 * 8]) = src[r * 16 + c4];
        }
    }
    __syncthreads();

    int wid = tid >> 5, lane = tid & 31;
    int wm0 = (wid & 1) * 64;
    int wn0 = (wid >> 1) * 32;
    int lg  = lane >> 2;
    int lt  = lane & 3;

    float c[4][4][4];
    #pragma unroll
    for (int i = 0; i < 4; i++)
        #pragma unroll
        for (int j = 0; j < 4; j++)
            #pragma unroll
            for (int q = 0; q < 4; q++) c[i][j][q] = 0.f;

    #pragma unroll
    for (int ks = 0; ks < 8; ks++) {
        int kb = ks * 16;
        unsigned a[4][4], b[4][2];
        #pragma unroll
        for (int mt = 0; mt < 4; mt++) {
            int r = wm0 + mt * 16 + lg;
            a[mt][0] = *reinterpret_cast<unsigned*>(&As[r * FQW + kb + 2*lt]);
            a[mt][1] = *reinterpret_cast<unsigned*>(&As[(r + 8) * FQW + kb + 2*lt]);
            a[mt][2] = *reinterpret_cast<unsigned*>(&As[r * FQW + kb + 2*lt + 8]);
            a[mt][3] = *reinterpret_cast<unsigned*>(&As[(r + 8) * FQW + kb + 2*lt + 8]);
        }
        #pragma unroll
        for (int nt = 0; nt < 4; nt++) {
            int cn = wn0 + nt * 8 + lg;
            b[nt][0] = *reinterpret_cast<unsigned*>(&Bs[cn * FQW + kb + 2*lt]);
            b[nt][1] = *reinterpret_cast<unsigned*>(&Bs[cn * FQW + kb + 2*lt + 8]);
        }
        #pragma unroll
        for (int mt = 0; mt < 4; mt++)
            #pragma unroll
            for (int nt = 0; nt < 4; nt++)
                mmaf16(c[mt][nt], a[mt], b[nt]);
    }

    #pragma unroll
    for (int mt = 0; mt < 4; mt++) {
        #pragma unroll
        for (int ri = 0; ri < 2; ri++) {
            int rl = wm0 + mt * 16 + lg + ri * 8;
            int en = ent[rl];
            if (en < 0) continue;
            int token = en >> 3;
            float* orow = out + (size_t)token * OUT;
            #pragma unroll
            for (int nt = 0; nt < 4; nt++) {
                int cc = n0 + wn0 + nt * 8 + 2 * lt;
                red2(&orow[cc], c[mt][nt][ri * 2 + 0], c[mt][nt][ri * 2 + 1]);
            }
        }
    }
}

// ---------------- bucket build ----------------------------------------------
__global__ void qbucket_kernel()
{
    int i = blockIdx.x * 256 + threadIdx.x;
    if (i >= BT * NH) return;
    int e = g_selidx[i];
    int pos = atomicAdd(&g_cnt[e], 1);
    g_list[e * BT + pos] = i;
}

// ---------------- fused flash attention + relative-position band -------------
#define GW 198
__global__ __launch_bounds__(256)
void flash_kernel()
{
    extern __shared__ char smc[];
    half*     Qs   = (half*)smc;                        // 64 x 136
    half*     Ps   = Qs + 64*FQW;                       // 64 x 136
    half*     Kt   = Ps + 64*FQW;                       // 128 x 136
    half*     Kp   = Kt + 128*FQW;                      // 192 x 136 (kpos window)
    unsigned* Vt2  = (unsigned*)(Kp + 192*FQW);         // 64 x 136 (paired V)
    float*    Gs   = (float*)(Vt2 + 64*FQW);            // 64 x 198
    float*    redm = Gs + 64*GW;                        // 256
    float*    reds = redm + 256;                        // 256

    int zh = blockIdx.y;
    int b  = zh >> 3, h = zh & 7;
    int s0 = blockIdx.x * 64;
    int tid = threadIdx.x;
    int wid = tid >> 5, lane = tid & 31;
    int lg = lane >> 2, lt = lane & 3;
    int wm0 = (wid & 1) * 32;
    int wn0 = (wid >> 1) * 32;
    // G warp tiling: 16-row group + 9-tile half-window anchored at ws
    int gm = (wid & 3) * 16;
    int ws = 48 - gm;
    int ghalf = wid >> 2;
    int gc0 = ws + ghalf * 72;

    // Q tile 64x128 halves, direct fp16 copy
    {
        const uint4* qbase = reinterpret_cast<const uint4*>(g_qh + (size_t)(zh * SS + s0) * 64);
        #pragma unroll
        for (int it = 0; it < 4; it++) {
            int lin = it * 256 + tid;
            int r = lin >> 4, c4 = lin & 15;
            *reinterpret_cast<uint4*>(&Qs[r * FQW + c4 * 8]) = qbase[r * 16 + c4];
        }
    }

    float o[2][4][4];
    float mrow[2][2], lrow[2][2];
    #pragma unroll
    for (int mt = 0; mt < 2; mt++) {
        mrow[mt][0] = mrow[mt][1] = -1e30f;
        lrow[mt][0] = lrow[mt][1] = 0.f;
        #pragma unroll
        for (int nt = 0; nt < 4; nt++)
            #pragma unroll
            for (int q = 0; q < 4; q++) o[mt][nt][q] = 0.f;
    }

    for (int kt = 0; kt < 8; kt++) {
        int t0  = kt * 128;
        int bt0 = b * SS + t0;
        int base = t0 - s0 + 960;
        // K tile 128x128 halves, direct copy
        {
            const uint4* kbase = reinterpret_cast<const uint4*>(g_kh + (size_t)bt0 * 64);
            #pragma unroll
            for (int it = 0; it < 8; it++) {
                int lin = it * 256 + tid;
                int r = lin >> 4, c4 = lin & 15;
                *reinterpret_cast<uint4*>(&Kt[r * FQW + c4 * 8]) = kbase[r * 16 + c4];
            }
        }
        // V tile paired from fp16
        {
            const unsigned* vbase = g_vh + (size_t)bt0 * 64;
            #pragma unroll
            for (int it = 0; it < 8; it++) {
                int lin = it * 256 + tid;
                int tp = lin >> 5, p0 = (lin & 31) * 4;
                uint2 x = *reinterpret_cast<const uint2*>(vbase + (size_t)(2*tp) * 64 + (p0 >> 1));
                uint2 y = *reinterpret_cast<const uint2*>(vbase + (size_t)(2*tp + 1) * 64 + (p0 >> 1));
                uint4 w;
                w.x = __byte_perm(x.x, y.x, 0x5410);
                w.y = __byte_perm(x.x, y.x, 0x7632);
                w.z = __byte_perm(x.y, y.y, 0x5410);
                w.w = __byte_perm(x.y, y.y, 0x7632);
                *reinterpret_cast<uint4*>(&Vt2[tp * FQW + p0]) = w;
            }
        }
        // kpos window 192 rows (fp16, L2-resident)
        {
            const uint4* kp4 = reinterpret_cast<const uint4*>(g_kpos_h);
            #pragma unroll
            for (int it = 0; it < 12; it++) {
                int lin = it * 256 + tid;
                int w = lin >> 4, c4 = lin & 15;
                uint4 v = kp4[(size_t)(base + w) * 16 + c4];
                *reinterpret_cast<uint4*>(&Kp[w * FQW + c4 * 8]) = v;
            }
        }
        __syncthreads();

        // --- G = Q @ Kp^T, band-trimmed: 16 rows x 72 cols per warp ---
        {
            float gg[9][4];
            #pragma unroll
            for (int nt = 0; nt < 9; nt++)
                #pragma unroll
                for (int q = 0; q < 4; q++) gg[nt][q] = 0.f;
            #pragma unroll
            for (int ks = 0; ks < 8; ks++) {
                int kb = ks * 16;
                unsigned a[4], bf[9][2];
                a[0] = *reinterpret_cast<unsigned*>(&Qs[(gm + lg) * FQW + kb + 2*lt]);
                a[1] = *reinterpret_cast<unsigned*>(&Qs[(gm + 8 + lg) * FQW + kb + 2*lt]);
                a[2] = *reinterpret_cast<unsigned*>(&Qs[(gm + lg) * FQW + kb + 2*lt + 8]);
                a[3] = *reinterpret_cast<unsigned*>(&Qs[(gm + 8 + lg) * FQW + kb + 2*lt + 8]);
                #pragma unroll
                for (int nt = 0; nt < 9; nt++) {
                    int cn = gc0 + nt * 8 + lg;
                    bf[nt][0] = *reinterpret_cast<unsigned*>(&Kp[cn * FQW + kb + 2*lt]);
                    bf[nt][1] = *reinterpret_cast<unsigned*>(&Kp[cn * FQW + kb + 2*lt + 8]);
                }
                #pragma unroll
                for (int nt = 0; nt < 9; nt++)
                    mmaf16(gg[nt], a, bf[nt]);
            }
            #pragma unroll
            for (int nt = 0; nt < 9; nt++) {
                int col = gc0 + nt * 8 + 2 * lt;
                *reinterpret_cast<float2*>(&Gs[(gm + lg) * GW + col]) =
                    make_float2(gg[nt][0], gg[nt][1]);
                *reinterpret_cast<float2*>(&Gs[(gm + 8 + lg) * GW + col]) =
                    make_float2(gg[nt][2], gg[nt][3]);
            }
        }

        // --- S = Q K^T ---
        float s_[2][4][4];
        #pragma unroll
        for (int mt = 0; mt < 2; mt++)
            #pragma unroll
            for (int nt = 0; nt < 4; nt++)
                #pragma unroll
                for (int q = 0; q < 4; q++) s_[mt][nt][q] = 0.f;
        #pragma unroll
        for (int ks = 0; ks < 8; ks++) {
            int kb = ks * 16;
            unsigned a[2][4], bf[4][2];
            #pragma unroll
            for (int mt = 0; mt < 2; mt++) {
                int r = wm0 + mt * 16 + lg;
                a[mt][0] = *reinterpret_cast<unsigned*>(&Qs[r * FQW + kb + 2*lt]);
                a[mt][1] = *reinterpret_cast<unsigned*>(&Qs[(r + 8) * FQW + kb + 2*lt]);
                a[mt][2] = *reinterpret_cast<unsigned*>(&Qs[r * FQW + kb + 2*lt + 8]);
                a[mt][3] = *reinterpret_cast<unsigned*>(&Qs[(r + 8) * FQW + kb + 2*lt + 8]);
            }
            #pragma unroll
            for (int nt = 0; nt < 4; nt++) {
                int cn = wn0 + nt * 8 + lg;
                bf[nt][0] = *reinterpret_cast<unsigned*>(&Kt[cn * FQW + kb + 2*lt]);
                bf[nt][1] = *reinterpret_cast<unsigned*>(&Kt[cn * FQW + kb + 2*lt + 8]);
            }
            #pragma unroll
            for (int mt = 0; mt < 2; mt++)
                #pragma unroll
                for (int nt = 0; nt < 4; nt++)
                    mmaf16(s_[mt][nt], a[mt], bf[nt]);
        }
        __syncthreads();   // Gs complete

        // band add: S[i,j] += G[i, j-i+63]
        #pragma unroll
        for (int mt = 0; mt < 2; mt++) {
            #pragma unroll
            for (int ri = 0; ri < 2; ri++) {
                int i = wm0 + mt * 16 + lg + ri * 8;
                const float* grow = Gs + (size_t)i * GW - i + 63;
                #pragma unroll
                for (int nt = 0; nt < 4; nt++) {
                    int j = wn0 + nt * 8 + 2 * lt;
                    s_[mt][nt][ri * 2 + 0] += grow[j];
                    s_[mt][nt][ri * 2 + 1] += grow[j + 1];
                }
            }
        }

        // row max
        #pragma unroll
        for (int mt = 0; mt < 2; mt++) {
            #pragma unroll
            for (int ri = 0; ri < 2; ri++) {
                float v = -1e30f;
                #pragma unroll
                for (int nt = 0; nt < 4; nt++)
                    v = fmaxf(v, fmaxf(s_[mt][nt][ri * 2], s_[mt][nt][ri * 2 + 1]));
                v = fmaxf(v, __shfl_xor_sync(0xffffffff, v, 1));
                v = fmaxf(v, __shfl_xor_sync(0xffffffff, v, 2));
                if (lt == 0) {
                    int rl = wm0 + mt * 16 + lg + ri * 8;
                    redm[rl * 4 + (wid >> 1)] = v;
                }
            }
        }
        __syncthreads();

        float scl[2][2];
        #pragma unroll
        for (int mt = 0; mt < 2; mt++) {
            #pragma unroll
            for (int ri = 0; ri < 2; ri++) {
                int rl = wm0 + mt * 16 + lg + ri * 8;
                float v = fmaxf(fmaxf(redm[rl * 4 + 0], redm[rl * 4 + 1]),
                                fmaxf(redm[rl * 4 + 2], redm[rl * 4 + 3]));
                float mnew = fmaxf(mrow[mt][ri], v);
                scl[mt][ri] = __expf(mrow[mt][ri] - mnew);
                mrow[mt][ri] = mnew;
            }
        }

        #pragma unroll
        for (int mt = 0; mt < 2; mt++) {
            #pragma unroll
            for (int ri = 0; ri < 2; ri++) {
                float m = mrow[mt][ri];
                float sum = 0.f;
                int r = wm0 + mt * 16 + lg + ri * 8;
                #pragma unroll
                for (int nt = 0; nt < 4; nt++) {
                    float e0 = __expf(s_[mt][nt][ri * 2 + 0] - m);
                    float e1 = __expf(s_[mt][nt][ri * 2 + 1] - m);
                    sum += e0 + e1;
                    int c0 = wn0 + nt * 8 + 2 * lt;
                    *reinterpret_cast<unsigned*>(&Ps[r * FQW + c0]) = pk2(e0, e1);
                    o[mt][nt][ri * 2 + 0] *= scl[mt][ri];
                    o[mt][nt][ri * 2 + 1] *= scl[mt][ri];
                }
                sum += __shfl_xor_sync(0xffffffff, sum, 1);
                sum += __shfl_xor_sync(0xffffffff, sum, 2);
                if (lt == 0) reds[r * 4 + (wid >> 1)] = sum;
            }
        }
        __syncthreads();

        #pragma unroll
        for (int mt = 0; mt < 2; mt++) {
            #pragma unroll
            for (int ri = 0; ri < 2; ri++) {
                int rl = wm0 + mt * 16 + lg + ri * 8;
                float ltile = reds[rl * 4 + 0] + reds[rl * 4 + 1]
                            + reds[rl * 4 + 2] + reds[rl * 4 + 3];
                lrow[mt][ri] = lrow[mt][ri] * scl[mt][ri] + ltile;
            }
        }

        // O += P @ V
        #pragma unroll
        for (int ks = 0; ks < 8; ks++) {
            int kb = ks * 16;
            unsigned a[2][4], bf[4][2];
            #pragma unroll
            for (int mt = 0; mt < 2; mt++) {
                int r = wm0 + mt * 16 + lg;
                a[mt][0] = *reinterpret_cast<unsigned*>(&Ps[r * FQW + kb + 2*lt]);
                a[mt][1] = *reinterpret_cast<unsigned*>(&Ps[(r + 8) * FQW + kb + 2*lt]);
                a[mt][2] = *reinterpret_cast<unsigned*>(&Ps[r * FQW + kb + 2*lt + 8]);
                a[mt][3] = *reinterpret_cast<unsigned*>(&Ps[(r + 8) * FQW + kb + 2*lt + 8]);
            }
            #pragma unroll
            for (int nt = 0; nt < 4; nt++) {
                int col = wn0 + nt * 8 + lg;
                bf[nt][0] = Vt2[(kb/2 + lt) * FQW + col];
                bf[nt][1] = Vt2[(kb/2 + lt + 4) * FQW + col];
            }
            #pragma unroll
            for (int mt = 0; mt < 2; mt++)
                #pragma unroll
                for (int nt = 0; nt < 4; nt++)
                    mmaf16(o[mt][nt], a[mt], bf[nt]);
        }
        __syncthreads();
    }

    // epilogue: normalize, gate, write fp16 rows to g_r[(token*NH+h)]
    #pragma unroll
    for (int mt = 0; mt < 2; mt++) {
        #pragma unroll
        for (int ri = 0; ri < 2; ri++) {
            int sglob = s0 + wm0 + mt * 16 + lg + ri * 8;
            int token = b * SS + sglob;
            float g = g_selval[token * NH + h];
            float inv = g / lrow[mt][ri];
            unsigned* rrow = g_r + ((size_t)token * NH + h) * 64;
            #pragma unroll
            for (int nt = 0; nt < 4; nt++) {
                int c0 = wn0 + nt * 8 + 2 * lt;
                rrow[c0 >> 1] = pk2(o[mt][nt][ri * 2 + 0] * inv,
                                    o[mt][nt][ri * 2 + 1] * inv);
            }
        }
    }
}

// ---------------- sel = curr @ sel_dst^T, top-8, sigmoid --------------------
__global__ void sel_topk_kernel(const float* __restrict__ curr,
                                const float* __restrict__ sdst)
{
    __shared__ float srow[IN];
    __shared__ float wsum[NE][4];
    __shared__ float vals[NE];
    int bs = blockIdx.x;
    int tid = threadIdx.x;
    const float* row = curr + (long)bs * IN;
    for (int i = tid; i < IN; i += 128) srow[i] = row[i];
    __syncthreads();

    float acc[NE];
    #pragma unroll
    for (int e = 0; e < NE; e++) acc[e] = 0.f;
    for (int i = tid; i < IN; i += 128) {
        float c = srow[i];
        #pragma unroll
        for (int e = 0; e < NE; e++)
            acc[e] = fmaf(c, sdst[e*IN + i], acc[e]);
    }
    int lane = tid & 31, w = tid >> 5;
    #pragma unroll
    for (int e = 0; e < NE; e++) {
        float v = acc[e];
        #pragma unroll
        for (int o = 16; o > 0; o >>= 1) v += __shfl_xor_sync(0xffffffff, v, o);
        if (lane == 0) wsum[e][w] = v;
    }
    __syncthreads();
    if (tid < NE) vals[tid] = wsum[tid][0] + wsum[tid][1] + wsum[tid][2] + wsum[tid][3];
    __syncthreads();
    if (tid == 0) {
        bool used[NE];
        #pragma unroll
        for (int e = 0; e < NE; e++) used[e] = false;
        for (int h = 0; h < NH; h++) {
            int bi = 0; float bv = -3.4e38f;
            for (int e = 0; e < NE; e++)
                if (!used[e] && vals[e] > bv) { bv = vals[e]; bi = e; }
            used[bi] = true;
            g_selidx[bs*NH + h] = bi;
            g_selval[bs*NH + h] = 1.f / (1.f + expf(-bv));
        }
    }
}

// ---------------- sinusoidal embedding --------------------------------------
__global__ void pemb_kernel()
{
    int i = blockIdx.x;
    int tid = threadIdx.x;
    float pos = (float)i - (float)(SS - 1);
    float cst = -logf(10000.f) / (float)IN;
    for (int j = tid; j < IN/2; j += 256) {
        float dv = expf((float)(2*j) * cst);
        float s, co;
        sincosf(pos * dv, &s, &co);
        g_pemb[(long)i*IN + 2*j]     = s;
        g_pemb[(long)i*IN + 2*j + 1] = co;
    }
}

// ---------------- launch ----------------------------------------------------
static char* symc(const void* sym) { void* p = nullptr; cudaGetSymbolAddress(&p, sym); return (char*)p; }

extern "C" void kernel_launch(void* const* d_in, const int* in_sizes, int n_in,
                              void* d_out, int out_size)
{
    const float* curr  = (const float*)d_in[0];
    const float* attn  = (const float*)d_in[1];
    const float* dtq   = (const float*)d_in[2];
    const float* dtkv  = (const float*)d_in[3];
    const float* oproj = (const float*)d_in[4];
    const float* ptpk  = (const float*)d_in[5];
    const float* sdst  = (const float*)d_in[6];
    const float* scale = (const float*)d_in[7];
    float* out = (float*)d_out;

    float* p_pemb   = (float*)symc(g_pemb);
    char*  p_cnt    = symc(g_cnt);
    char*  p_kpos_h = symc(g_kpos_h);

    static int init_done = 0;
    static cudaStream_t s1, s2;
    static cudaEvent_t evRoot, ev1, ev2;
    const int FLASH_SMEM = (64*FQW + 64*FQW + 128*FQW + 192*FQW)*2
                         + 64*FQW*4
                         + 64*GW*4 + 512*4;
    const int OB_SMEM = 2*128*FQW*2 + 128*4;
    if (!init_done) {
        cudaFuncSetAttribute(flash_kernel,
            cudaFuncAttributeMaxDynamicSharedMemorySize, FLASH_SMEM);
        cudaFuncSetAttribute(tgemm<0>,
            cudaFuncAttributeMaxDynamicSharedMemorySize, TG_SMEM);
        cudaFuncSetAttribute(tgemm<1>,
            cudaFuncAttributeMaxDynamicSharedMemorySize, TG_SMEM);
        cudaFuncSetAttribute(qexp_kernel,
            cudaFuncAttributeMaxDynamicSharedMemorySize, QX_SMEM);
        cudaFuncSetAttribute(obucket_kernel,
            cudaFuncAttributeMaxDynamicSharedMemorySize, OB_SMEM);
        cudaStreamCreateWithFlags(&s1, cudaStreamNonBlocking);
        cudaStreamCreateWithFlags(&s2, cudaStreamNonBlocking);
        cudaEventCreateWithFlags(&evRoot, cudaEventDisableTiming);
        cudaEventCreateWithFlags(&ev1, cudaEventDisableTiming);
        cudaEventCreateWithFlags(&ev2, cudaEventDisableTiming);
        init_done = 1;
    }

    // fork
    cudaEventRecord(evRoot, 0);
    cudaStreamWaitEvent(s1, evRoot, 0);
    cudaStreamWaitEvent(s2, evRoot, 0);

    // s1: expert selection + buckets + q projection
    cudaMemsetAsync(p_cnt, 0, NE * sizeof(int), s1);
    sel_topk_kernel<<<BT, 128, 0, s1>>>(curr, sdst);
    qbucket_kernel<<<(BT*NH + 255)/256, 256, 0, s1>>>();
    qexp_kernel<<<dim3(1, 32, NE), 256, QX_SMEM, s1>>>(curr, dtq, scale);
    cudaEventRecord(ev1, s1);

    // s2: positional embedding + kpos + kv
    pemb_kernel<<<RLEN, 256, 0, s2>>>();
    cudaMemsetAsync(p_kpos_h + (size_t)RLEN * 64 * 4, 0, 64 * 4, s2);
    tgemm<1><<<dim3(1, 16, 1), 256, TG_SMEM, s2>>>(p_pemb, ptpk, nullptr,
        RLEN, PROJ, IN, IN, IN, PROJ, scale, 3);
    tgemm<0><<<dim3(2, 32, 1), 256, TG_SMEM, s2>>>(attn, dtkv, nullptr,
        BT, 2*PROJ, IN, IN, 2*PROJ, 2*PROJ, scale, 2);
    cudaEventRecord(ev2, s2);

    // default: zero out + transpose oproj while producers run, then join
    cudaMemsetAsync(out, 0, (size_t)BT * OUT * sizeof(float));
    oconv_kernel<<<dim3(OUT/32, PROJ/32, NE), 256>>>(oproj);
    cudaStreamWaitEvent(0, ev1, 0);
    cudaStreamWaitEvent(0, ev2, 0);

    // fused attention
    flash_kernel<<<dim3(16, BB*NH), 256, FLASH_SMEM>>>();

    // bucketed output projection (red.v2 accumulate over heads)
    obucket_kernel<<<dim3(8, 32, NE), 256, OB_SMEM>>>(out);
}